// round 9
// baseline (speedup 1.0000x reference)
#include <cuda_runtime.h>
#include <cstdint>
#include <cstddef>

#define Vv   32000
#define Ee   1024
#define Hh   1024
#define Bb   32
#define SEe  256
#define SDd  128
#define G3   3072
#define NBLK 96

__device__ float g_enc_gi[(size_t)SEe * Bb * G3];
__device__ float g_dec_gx[(size_t)SDd * Bb * G3];
__device__ float g_enc_out[(size_t)SEe * Bb * Hh];
__device__ float g_kT[(size_t)Bb * SEe * Hh];
__device__ float g_dec_out[(size_t)SDd * Bb * Hh];
__device__ float g_h0[Bb * Hh];
__device__ float g_h1[Bb * Hh];
__device__ float g_ctx[Bb * Hh];
__device__ float g_sc[Bb * SEe];
__device__ float g_qp[2 * (size_t)Bb * Hh];
__device__ float g_ghp[2 * (size_t)Bb * G3];
__device__ float g_gcp[2 * (size_t)Bb * G3];
__device__ int   g_enc_rows[SEe * Bb];
__device__ int   g_dec_rows[SDd * Bb];
__device__ unsigned g_bar_count;
__device__ unsigned g_bar_sense;

__device__ __forceinline__ float sigf(float x) { return 1.f / (1.f + expf(-x)); }

// software grid barrier: all NBLK blocks co-resident (wave-1, grid <= SM count).
// Tight LDG spin (no __nanosleep — its wake quantum/jitter dominated barrier cost).
__device__ __forceinline__ void grid_bar(unsigned target)
{
    __syncthreads();
    if (threadIdx.x == 0) {
        __threadfence();
        if (atomicAdd(&g_bar_count, 1u) == NBLK - 1) {
            atomicExch(&g_bar_count, 0u);
            __threadfence();
            atomicExch(&g_bar_sense, target);
        } else {
            while (*(volatile unsigned*)&g_bar_sense < target) { }
            __threadfence();
        }
    }
    __syncthreads();
}

__global__ void __launch_bounds__(256) build_rows_kernel(
    const int* __restrict__ enc_in, const int* __restrict__ dec_in)
{
    int m = blockIdx.x * 256 + threadIdx.x;
    if (m < SEe * Bb) {
        int t = m >> 5, b = m & 31;
        g_enc_rows[m] = enc_in[b * SEe + t];
    }
    if (m < SDd * Bb) {
        int t = m >> 5, b = m & 31;
        g_dec_rows[m] = dec_in[b * SDd + t];
    }
}

__global__ void __launch_bounds__(256) init_h_kernel()
{
    int i = blockIdx.x * 256 + threadIdx.x;
    if (i < Bb * Hh) g_h0[i] = 0.f;
}

// ================= tf32 tensor-core GEMM =================
__device__ __forceinline__ float to_tf32(float x)
{
    uint32_t u;
    asm("cvt.rna.tf32.f32 %0, %1;" : "=r"(u) : "f"(x));
    return __uint_as_float(u);
}

__device__ __forceinline__ float4 cvt4(float4 v)
{
    float4 r;
    r.x = to_tf32(v.x); r.y = to_tf32(v.y); r.z = to_tf32(v.z); r.w = to_tf32(v.w);
    return r;
}

__device__ __forceinline__ void mma_tf32(float* c, const float* a, const float* b)
{
    asm volatile(
        "mma.sync.aligned.m16n8k8.row.col.f32.tf32.tf32.f32 "
        "{%0,%1,%2,%3}, {%4,%5,%6,%7}, {%8,%9}, {%0,%1,%2,%3};"
        : "+f"(c[0]), "+f"(c[1]), "+f"(c[2]), "+f"(c[3])
        : "r"(__float_as_uint(a[0])), "r"(__float_as_uint(a[1])),
          "r"(__float_as_uint(a[2])), "r"(__float_as_uint(a[3])),
          "r"(__float_as_uint(b[0])), "r"(__float_as_uint(b[1])));
}

// C[remap(m)][n] = bias[n] + sum_k A[arows?arows[m]:m][k] * W[n][k]
__global__ void __launch_bounds__(256) gemm_tf32(
    const float* __restrict__ A, const int* __restrict__ arows, int lda,
    const float* __restrict__ W, int ldw,
    const float* __restrict__ bias,
    float* __restrict__ C, int N, int K, int Sremap)
{
    __shared__ __align__(16) float As[2][128][20];
    __shared__ __align__(16) float Bs[2][128][20];

    int tid = threadIdx.x;
    int bm = blockIdx.y * 128, bn = blockIdx.x * 128;
    int lr = tid >> 2;
    int lk = (tid & 3) << 2;

    int ar0 = arows ? arows[bm + lr] : bm + lr;
    int ar1 = arows ? arows[bm + lr + 64] : bm + lr + 64;
    const float* arow0 = A + (size_t)ar0 * lda + lk;
    const float* arow1 = A + (size_t)ar1 * lda + lk;
    const float* wrow0 = W + (size_t)(bn + lr) * ldw + lk;
    const float* wrow1 = W + (size_t)(bn + lr + 64) * ldw + lk;

    int warp = tid >> 5, lane = tid & 31;
    int wm = (warp >> 1) * 32, wn = (warp & 1) * 64;
    int g = lane >> 2, tg = lane & 3;

    float acc[2][8][4];
#pragma unroll
    for (int mt = 0; mt < 2; mt++)
#pragma unroll
        for (int nt = 0; nt < 8; nt++)
#pragma unroll
            for (int i = 0; i < 4; i++) acc[mt][nt][i] = 0.f;

    float4 a0 = *(const float4*)arow0;
    float4 a1 = *(const float4*)arow1;
    float4 b0 = *(const float4*)wrow0;
    float4 b1 = *(const float4*)wrow1;

    int buf = 0;
    for (int k0 = 0; k0 < K; k0 += 16) {
        *(float4*)&As[buf][lr][lk]      = cvt4(a0);
        *(float4*)&As[buf][lr + 64][lk] = cvt4(a1);
        *(float4*)&Bs[buf][lr][lk]      = cvt4(b0);
        *(float4*)&Bs[buf][lr + 64][lk] = cvt4(b1);
        __syncthreads();
        if (k0 + 16 < K) {
            a0 = *(const float4*)(arow0 + k0 + 16);
            a1 = *(const float4*)(arow1 + k0 + 16);
            b0 = *(const float4*)(wrow0 + k0 + 16);
            b1 = *(const float4*)(wrow1 + k0 + 16);
        }
#pragma unroll
        for (int ks = 0; ks < 2; ks++) {
            float af[2][4], bf[8][2];
#pragma unroll
            for (int mt = 0; mt < 2; mt++) {
                const float* p0 = &As[buf][wm + mt * 16 + g][ks * 8 + tg];
                const float* p1 = &As[buf][wm + mt * 16 + g + 8][ks * 8 + tg];
                af[mt][0] = p0[0]; af[mt][1] = p1[0];
                af[mt][2] = p0[4]; af[mt][3] = p1[4];
            }
#pragma unroll
            for (int nt = 0; nt < 8; nt++) {
                const float* p = &Bs[buf][wn + nt * 8 + g][ks * 8 + tg];
                bf[nt][0] = p[0]; bf[nt][1] = p[4];
            }
#pragma unroll
            for (int mt = 0; mt < 2; mt++)
#pragma unroll
                for (int nt = 0; nt < 8; nt++)
                    mma_tf32(acc[mt][nt], af[mt], bf[nt]);
        }
        buf ^= 1;
    }

#pragma unroll
    for (int mt = 0; mt < 2; mt++) {
        int m0 = bm + wm + mt * 16 + g;
#pragma unroll
        for (int half = 0; half < 2; half++) {
            int m = m0 + half * 8;
            size_t orow = (Sremap > 0) ? ((size_t)(m & 31) * Sremap + (size_t)(m >> 5)) : (size_t)m;
            float* crow = C + orow * (size_t)N;
#pragma unroll
            for (int nt = 0; nt < 8; nt++) {
                int col = bn + wn + nt * 8 + tg * 2;
                float bv0 = bias ? bias[col]     : 0.f;
                float bv1 = bias ? bias[col + 1] : 0.f;
                float2 v;
                v.x = acc[mt][nt][half * 2 + 0] + bv0;
                v.y = acc[mt][nt][half * 2 + 1] + bv1;
                *(float2*)&crow[col] = v;
            }
        }
    }
}

// ================= skinny GEMM partial (recurrent steps) =================
// out[b][cb+c] (partial over K slice [kbase, kbase+512)) = sum A[b][k]*W[cb+c][k]
__device__ __forceinline__ void skinny64(
    const float* __restrict__ A,
    const float* __restrict__ W, int ldw,
    int cb, int kbase,
    float* __restrict__ outp, int oldd,
    float (*as)[68], float (*ws)[68])
{
    const int tid = threadIdx.x;
    const int ar = tid >> 3;
    const int ak = (tid & 7) << 3;
    const int wr = tid >> 2;
    const int wk = (tid & 3) << 4;
    const int wrx = wr ^ ((wk >> 1) & 24);
    const int ob = (tid >> 4) << 1;
    const int oc = (tid & 15) << 2;

    const float* Ap = A + (size_t)ar * Hh + kbase + ak;
    const float* Wp = W + (size_t)(cb + wr) * ldw + kbase + wk;

    float4 a0 = *(const float4*)Ap;
    float4 a1 = *(const float4*)(Ap + 4);
    float4 w0 = *(const float4*)Wp;
    float4 w1 = *(const float4*)(Wp + 4);
    float4 w2 = *(const float4*)(Wp + 8);
    float4 w3 = *(const float4*)(Wp + 12);

    float acc0[4] = {0.f, 0.f, 0.f, 0.f};
    float acc1[4] = {0.f, 0.f, 0.f, 0.f};

    for (int k0 = 0; k0 < 512; k0 += 64) {
        __syncthreads();
        *(float4*)&as[ar][ak]     = a0;
        *(float4*)&as[ar][ak + 4] = a1;
        ws[wk +  0][wrx] = w0.x; ws[wk +  1][wrx] = w0.y; ws[wk +  2][wrx] = w0.z; ws[wk +  3][wrx] = w0.w;
        ws[wk +  4][wrx] = w1.x; ws[wk +  5][wrx] = w1.y; ws[wk +  6][wrx] = w1.z; ws[wk +  7][wrx] = w1.w;
        ws[wk +  8][wrx] = w2.x; ws[wk +  9][wrx] = w2.y; ws[wk + 10][wrx] = w2.z; ws[wk + 11][wrx] = w2.w;
        ws[wk + 12][wrx] = w3.x; ws[wk + 13][wrx] = w3.y; ws[wk + 14][wrx] = w3.z; ws[wk + 15][wrx] = w3.w;
        __syncthreads();
        if (k0 + 64 < 512) {
            a0 = *(const float4*)(Ap + k0 + 64);
            a1 = *(const float4*)(Ap + k0 + 68);
            w0 = *(const float4*)(Wp + k0 + 64);
            w1 = *(const float4*)(Wp + k0 + 68);
            w2 = *(const float4*)(Wp + k0 + 72);
            w3 = *(const float4*)(Wp + k0 + 76);
        }
#pragma unroll 16
        for (int kk = 0; kk < 64; kk++) {
            float4 w4 = *(const float4*)&ws[kk][oc ^ ((kk >> 1) & 24)];
            float aa = as[ob][kk];
            float ab = as[ob + 1][kk];
            acc0[0] += aa * w4.x; acc0[1] += aa * w4.y; acc0[2] += aa * w4.z; acc0[3] += aa * w4.w;
            acc1[0] += ab * w4.x; acc1[1] += ab * w4.y; acc1[2] += ab * w4.z; acc1[3] += ab * w4.w;
        }
    }

    float* o0 = outp + (size_t)ob * oldd + cb + oc;
    *(float4*)o0 = make_float4(acc0[0], acc0[1], acc0[2], acc0[3]);
    *(float4*)(o0 + oldd) = make_float4(acc1[0], acc1[1], acc1[2], acc1[3]);
}

// ================= persistent encoder =================
__global__ void __launch_bounds__(256) enc_persistent(
    const float* __restrict__ Whh, const float* __restrict__ bhh,
    const int* __restrict__ enclen)
{
    __shared__ unsigned s_base;
    __shared__ __align__(16) float as[32][68];
    __shared__ __align__(16) float ws[64][68];
    int tid = threadIdx.x, bid = blockIdx.x;
    if (tid == 0) s_base = *(volatile unsigned*)&g_bar_sense;
    __syncthreads();
    unsigned ep = s_base;

    for (int t = 0; t < SEe; t++) {
        const float* h  = (t & 1) ? g_h1 : g_h0;
        float*       hn = (t & 1) ? g_h0 : g_h1;

        skinny64(h, Whh, Hh, (bid >> 1) * 64, (bid & 1) * 512,
                 g_ghp + (size_t)(bid & 1) * (Bb * G3), G3, as, ws);
        grid_bar(++ep);

        for (int idx = bid * 256 + tid; idx < Bb * Hh; idx += NBLK * 256) {
            int b = idx >> 10, j = idx & 1023;
            const float* gi  = g_enc_gi + (size_t)(t * Bb + b) * G3;
            const float* gh0 = g_ghp + (size_t)b * G3;
            const float* gh1 = g_ghp + (size_t)(Bb * G3) + (size_t)b * G3;
            float hr = gh0[j]          + gh1[j]          + bhh[j];
            float hz = gh0[Hh + j]     + gh1[Hh + j]     + bhh[Hh + j];
            float hv = gh0[2*Hh + j]   + gh1[2*Hh + j]   + bhh[2*Hh + j];
            float r = sigf(gi[j] + hr);
            float z = sigf(gi[Hh + j] + hz);
            float n = tanhf(gi[2*Hh + j] + r * hv);
            float hold = h[idx];
            float hnv = (1.f - z) * n + z * hold;
            bool msk = t < enclen[b];
            hn[idx] = msk ? hnv : hold;
            g_enc_out[(size_t)t * Bb * Hh + idx] = msk ? hnv : 0.f;
        }
        grid_bar(++ep);
    }
}

// ================= persistent decoder =================
__global__ void __launch_bounds__(256) dec_persistent(
    const float* __restrict__ qW, const float* __restrict__ qb,
    const float* __restrict__ Whh, const float* __restrict__ Wih,
    const float* __restrict__ bhh)
{
    __shared__ unsigned s_base;
    __shared__ __align__(16) float as[32][68];
    __shared__ __align__(16) float ws[64][68];
    __shared__ __align__(16) float qs[Hh];
    __shared__ float sc[SEe];
    __shared__ float red[8];
    int tid = threadIdx.x, bid = blockIdx.x, lane = tid & 31, warp = tid >> 5;
    if (tid == 0) s_base = *(volatile unsigned*)&g_bar_sense;
    __syncthreads();
    unsigned ep = s_base;

    const float* Wc = Wih + Ee;

    for (int t = 0; t < SDd; t++) {
        const float* h  = (t & 1) ? g_h1 : g_h0;
        float*       hn = (t & 1) ? g_h0 : g_h1;

        // A1: q partials (blocks 0..31) || gh cols 0..2047 partials (32..95)
        if (bid < 32) {
            skinny64(h, qW, Hh, (bid >> 1) * 64, (bid & 1) * 512,
                     g_qp + (size_t)(bid & 1) * (Bb * Hh), Hh, as, ws);
        } else {
            int tt = bid - 32;
            skinny64(h, Whh, Hh, (tt >> 1) * 64, (tt & 1) * 512,
                     g_ghp + (size_t)(tt & 1) * (Bb * G3), G3, as, ws);
        }
        grid_bar(++ep);

        // A2: scores, 3 blocks per batch, q folded into smem
        {
            int b = bid & 31, part = bid >> 5;
            const float* q0 = g_qp + (size_t)b * Hh;
            const float* q1 = g_qp + (size_t)(Bb * Hh) + (size_t)b * Hh;
            for (int j = tid; j < Hh; j += 256) qs[j] = q0[j] + q1[j] + qb[j];
            __syncthreads();
            int ss = part * 86;
            int se = ss + 86; if (se > SEe) se = SEe;
            const float4* qr = (const float4*)qs;
            for (int s = ss + warp; s < se; s += 8) {
                const float4* kr = (const float4*)(g_kT + ((size_t)b * SEe + s) * Hh);
                float a = 0.f;
#pragma unroll
                for (int i = 0; i < 8; i++) {
                    float4 kv = kr[lane + 32 * i];
                    float4 qv = qr[lane + 32 * i];
                    a += kv.x * qv.x + kv.y * qv.y + kv.z * qv.z + kv.w * qv.w;
                }
#pragma unroll
                for (int o = 16; o > 0; o >>= 1) a += __shfl_xor_sync(0xffffffffu, a, o);
                if (lane == 0) g_sc[b * SEe + s] = a;
            }
        }
        grid_bar(++ep);

        // A3: softmax + ctx halves (blocks 0..63) || gh cols 2048..3071 (64..95)
        if (bid < 64) {
            int b = bid >> 1, half = bid & 1;
            float v = g_sc[b * SEe + tid];
            float m = v;
#pragma unroll
            for (int o = 16; o > 0; o >>= 1) m = fmaxf(m, __shfl_xor_sync(0xffffffffu, m, o));
            if (lane == 0) red[warp] = m;
            __syncthreads();
            float mm = red[0];
#pragma unroll
            for (int i = 1; i < 8; i++) mm = fmaxf(mm, red[i]);
            float e = expf(v - mm);
            float ssum = e;
#pragma unroll
            for (int o = 16; o > 0; o >>= 1) ssum += __shfl_xor_sync(0xffffffffu, ssum, o);
            __syncthreads();
            if (lane == 0) red[warp] = ssum;
            __syncthreads();
            float tot = 0.f;
#pragma unroll
            for (int i = 0; i < 8; i++) tot += red[i];
            sc[tid] = e / tot;
            __syncthreads();

            int c0 = half * 512 + tid;
            float s0 = 0.f, s1 = 0.f;
#pragma unroll 8
            for (int s = 0; s < SEe; s++) {
                float a = sc[s];
                const float* er = g_enc_out + ((size_t)s * Bb + b) * Hh;
                s0 += a * er[c0];
                s1 += a * er[c0 + 256];
            }
            g_ctx[(size_t)b * Hh + c0]       = s0;
            g_ctx[(size_t)b * Hh + c0 + 256] = s1;
        } else {
            int tt = bid - 64;
            skinny64(h, Whh, Hh, 2048 + (tt >> 1) * 64, (tt & 1) * 512,
                     g_ghp + (size_t)(tt & 1) * (Bb * G3), G3, as, ws);
        }
        grid_bar(++ep);

        // A4: gc = ctx @ Wc.T partials
        skinny64(g_ctx, Wc, Ee + Hh, (bid >> 1) * 64, (bid & 1) * 512,
                 g_gcp + (size_t)(bid & 1) * (Bb * G3), G3, as, ws);
        grid_bar(++ep);

        // A5: gate + state update
        for (int idx = bid * 256 + tid; idx < Bb * Hh; idx += NBLK * 256) {
            int b = idx >> 10, j = idx & 1023;
            const float* gx  = g_dec_gx + (size_t)(t * Bb + b) * G3;
            const float* gh0 = g_ghp + (size_t)b * G3;
            const float* gh1 = g_ghp + (size_t)(Bb * G3) + (size_t)b * G3;
            const float* gc0 = g_gcp + (size_t)b * G3;
            const float* gc1 = g_gcp + (size_t)(Bb * G3) + (size_t)b * G3;
            float hr = gh0[j]        + gh1[j]        + bhh[j];
            float hz = gh0[Hh + j]   + gh1[Hh + j]   + bhh[Hh + j];
            float hv = gh0[2*Hh + j] + gh1[2*Hh + j] + bhh[2*Hh + j];
            float ir = gx[j]        + gc0[j]        + gc1[j];
            float iz = gx[Hh + j]   + gc0[Hh + j]   + gc1[Hh + j];
            float in = gx[2*Hh + j] + gc0[2*Hh + j] + gc1[2*Hh + j];
            float r = sigf(ir + hr);
            float z = sigf(iz + hz);
            float n = tanhf(in + r * hv);
            float hold = h[idx];
            float h2 = (1.f - z) * n + z * hold;
            hn[idx] = h2;
            g_dec_out[(size_t)t * Bb * Hh + idx] = h2;
        }
        grid_bar(++ep);
    }
}

extern "C" void kernel_launch(void* const* d_in, const int* in_sizes, int n_in,
                              void* d_out, int out_size)
{
    const int*   enc_in   = (const int*)d_in[0];
    const int*   dec_in   = (const int*)d_in[1];
    const int*   enc_len  = (const int*)d_in[2];
    const float* emb      = (const float*)d_in[4];
    const float* enc_Wih  = (const float*)d_in[5];
    const float* enc_Whh  = (const float*)d_in[6];
    const float* enc_bih  = (const float*)d_in[7];
    const float* enc_bhh  = (const float*)d_in[8];
    const float* dec_Wih  = (const float*)d_in[9];
    const float* dec_Whh  = (const float*)d_in[10];
    const float* dec_bih  = (const float*)d_in[11];
    const float* dec_bhh  = (const float*)d_in[12];
    const float* attn_kW  = (const float*)d_in[13];
    const float* attn_kb  = (const float*)d_in[14];
    const float* attn_qW  = (const float*)d_in[15];
    const float* attn_qb  = (const float*)d_in[16];
    const float* logits_W = (const float*)d_in[17];
    const float* logits_b = (const float*)d_in[18];
    float* out = (float*)d_out;
    (void)in_sizes; (void)n_in; (void)out_size;

    float *p_enc_gi, *p_dec_gx, *p_enc_out, *p_kT, *p_dec_out;
    int *p_enc_rows, *p_dec_rows;
    cudaGetSymbolAddress((void**)&p_enc_gi,  g_enc_gi);
    cudaGetSymbolAddress((void**)&p_dec_gx,  g_dec_gx);
    cudaGetSymbolAddress((void**)&p_enc_out, g_enc_out);
    cudaGetSymbolAddress((void**)&p_kT,      g_kT);
    cudaGetSymbolAddress((void**)&p_dec_out, g_dec_out);
    cudaGetSymbolAddress((void**)&p_enc_rows, g_enc_rows);
    cudaGetSymbolAddress((void**)&p_dec_rows, g_dec_rows);

    build_rows_kernel<<<32, 256>>>(enc_in, dec_in);
    init_h_kernel<<<(Bb * Hh) / 256, 256>>>();

    gemm_tf32<<<dim3(G3 / 128, (SEe * Bb) / 128), 256>>>(
        emb, p_enc_rows, Ee, enc_Wih, Ee, enc_bih, p_enc_gi, G3, Ee, 0);
    gemm_tf32<<<dim3(G3 / 128, (SDd * Bb) / 128), 256>>>(
        emb, p_dec_rows, Ee, dec_Wih, Ee + Hh, dec_bih, p_dec_gx, G3, Ee, 0);

    enc_persistent<<<NBLK, 256>>>(enc_Whh, enc_bhh, enc_len);

    gemm_tf32<<<dim3(Hh / 128, (SEe * Bb) / 128), 256>>>(
        p_enc_out, nullptr, Hh, attn_kW, Hh, attn_kb, p_kT, Hh, Hh, SEe);

    dec_persistent<<<NBLK, 256>>>(attn_qW, attn_qb, dec_Whh, dec_Wih, dec_bhh);

    gemm_tf32<<<dim3(Vv / 128, (SDd * Bb) / 128), 256>>>(
        p_dec_out, nullptr, Hh, logits_W, Hh, logits_b, out, Vv, Hh, SDd);
}

// round 10
// speedup vs baseline: 1.4811x; 1.4811x over previous
#include <cuda_runtime.h>
#include <cstdint>
#include <cstddef>

#define Vv   32000
#define Ee   1024
#define Hh   1024
#define Bb   32
#define SEe  256
#define SDd  128
#define G3   3072
#define NBLK 96
#define NBE  128

__device__ float g_enc_gi[(size_t)SEe * Bb * G3];
__device__ float g_dec_gx[(size_t)SDd * Bb * G3];
__device__ float g_enc_out[(size_t)SEe * Bb * Hh];
__device__ float g_kT[(size_t)Bb * SEe * Hh];
__device__ float g_dec_out[(size_t)SDd * Bb * Hh];
__device__ float g_h0[Bb * Hh];
__device__ float g_h1[Bb * Hh];
__device__ float g_ctx[Bb * Hh];
__device__ float g_sc[Bb * SEe];
__device__ float g_qp[2 * (size_t)Bb * Hh];
__device__ float g_ghp[2 * (size_t)Bb * G3];
__device__ float g_gcp[2 * (size_t)Bb * G3];
__device__ int   g_enc_rows[SEe * Bb];
__device__ int   g_dec_rows[SDd * Bb];
__device__ unsigned g_bar_count;
__device__ unsigned g_bar_sense;

__device__ __forceinline__ float sigf(float x) { return 1.f / (1.f + expf(-x)); }

// software grid barrier, nanosleep spin (tight spin regressed: DVFS clock drop).
__device__ __forceinline__ void grid_bar(unsigned target, unsigned nblk)
{
    __syncthreads();
    if (threadIdx.x == 0) {
        __threadfence();
        if (atomicAdd(&g_bar_count, 1u) == nblk - 1) {
            atomicExch(&g_bar_count, 0u);
            __threadfence();
            atomicExch(&g_bar_sense, target);
        } else {
            while (*(volatile unsigned*)&g_bar_sense < target) __nanosleep(64);
            __threadfence();
        }
    }
    __syncthreads();
}

__global__ void __launch_bounds__(256) build_rows_kernel(
    const int* __restrict__ enc_in, const int* __restrict__ dec_in)
{
    int m = blockIdx.x * 256 + threadIdx.x;
    if (m < SEe * Bb) {
        int t = m >> 5, b = m & 31;
        g_enc_rows[m] = enc_in[b * SEe + t];
    }
    if (m < SDd * Bb) {
        int t = m >> 5, b = m & 31;
        g_dec_rows[m] = dec_in[b * SDd + t];
    }
}

__global__ void __launch_bounds__(256) init_h_kernel()
{
    int i = blockIdx.x * 256 + threadIdx.x;
    if (i < Bb * Hh) g_h0[i] = 0.f;
}

// ================= tf32 tensor-core GEMM =================
__device__ __forceinline__ float to_tf32(float x)
{
    uint32_t u;
    asm("cvt.rna.tf32.f32 %0, %1;" : "=r"(u) : "f"(x));
    return __uint_as_float(u);
}

__device__ __forceinline__ float4 cvt4(float4 v)
{
    float4 r;
    r.x = to_tf32(v.x); r.y = to_tf32(v.y); r.z = to_tf32(v.z); r.w = to_tf32(v.w);
    return r;
}

__device__ __forceinline__ void mma_tf32(float* c, const float* a, const float* b)
{
    asm volatile(
        "mma.sync.aligned.m16n8k8.row.col.f32.tf32.tf32.f32 "
        "{%0,%1,%2,%3}, {%4,%5,%6,%7}, {%8,%9}, {%0,%1,%2,%3};"
        : "+f"(c[0]), "+f"(c[1]), "+f"(c[2]), "+f"(c[3])
        : "r"(__float_as_uint(a[0])), "r"(__float_as_uint(a[1])),
          "r"(__float_as_uint(a[2])), "r"(__float_as_uint(a[3])),
          "r"(__float_as_uint(b[0])), "r"(__float_as_uint(b[1])));
}

__global__ void __launch_bounds__(256) gemm_tf32(
    const float* __restrict__ A, const int* __restrict__ arows, int lda,
    const float* __restrict__ W, int ldw,
    const float* __restrict__ bias,
    float* __restrict__ C, int N, int K, int Sremap)
{
    __shared__ __align__(16) float As[2][128][20];
    __shared__ __align__(16) float Bs[2][128][20];

    int tid = threadIdx.x;
    int bm = blockIdx.y * 128, bn = blockIdx.x * 128;
    int lr = tid >> 2;
    int lk = (tid & 3) << 2;

    int ar0 = arows ? arows[bm + lr] : bm + lr;
    int ar1 = arows ? arows[bm + lr + 64] : bm + lr + 64;
    const float* arow0 = A + (size_t)ar0 * lda + lk;
    const float* arow1 = A + (size_t)ar1 * lda + lk;
    const float* wrow0 = W + (size_t)(bn + lr) * ldw + lk;
    const float* wrow1 = W + (size_t)(bn + lr + 64) * ldw + lk;

    int warp = tid >> 5, lane = tid & 31;
    int wm = (warp >> 1) * 32, wn = (warp & 1) * 64;
    int g = lane >> 2, tg = lane & 3;

    float acc[2][8][4];
#pragma unroll
    for (int mt = 0; mt < 2; mt++)
#pragma unroll
        for (int nt = 0; nt < 8; nt++)
#pragma unroll
            for (int i = 0; i < 4; i++) acc[mt][nt][i] = 0.f;

    float4 a0 = *(const float4*)arow0;
    float4 a1 = *(const float4*)arow1;
    float4 b0 = *(const float4*)wrow0;
    float4 b1 = *(const float4*)wrow1;

    int buf = 0;
    for (int k0 = 0; k0 < K; k0 += 16) {
        *(float4*)&As[buf][lr][lk]      = cvt4(a0);
        *(float4*)&As[buf][lr + 64][lk] = cvt4(a1);
        *(float4*)&Bs[buf][lr][lk]      = cvt4(b0);
        *(float4*)&Bs[buf][lr + 64][lk] = cvt4(b1);
        __syncthreads();
        if (k0 + 16 < K) {
            a0 = *(const float4*)(arow0 + k0 + 16);
            a1 = *(const float4*)(arow1 + k0 + 16);
            b0 = *(const float4*)(wrow0 + k0 + 16);
            b1 = *(const float4*)(wrow1 + k0 + 16);
        }
#pragma unroll
        for (int ks = 0; ks < 2; ks++) {
            float af[2][4], bf[8][2];
#pragma unroll
            for (int mt = 0; mt < 2; mt++) {
                const float* p0 = &As[buf][wm + mt * 16 + g][ks * 8 + tg];
                const float* p1 = &As[buf][wm + mt * 16 + g + 8][ks * 8 + tg];
                af[mt][0] = p0[0]; af[mt][1] = p1[0];
                af[mt][2] = p0[4]; af[mt][3] = p1[4];
            }
#pragma unroll
            for (int nt = 0; nt < 8; nt++) {
                const float* p = &Bs[buf][wn + nt * 8 + g][ks * 8 + tg];
                bf[nt][0] = p[0]; bf[nt][1] = p[4];
            }
#pragma unroll
            for (int mt = 0; mt < 2; mt++)
#pragma unroll
                for (int nt = 0; nt < 8; nt++)
                    mma_tf32(acc[mt][nt], af[mt], bf[nt]);
        }
        buf ^= 1;
    }

#pragma unroll
    for (int mt = 0; mt < 2; mt++) {
        int m0 = bm + wm + mt * 16 + g;
#pragma unroll
        for (int half = 0; half < 2; half++) {
            int m = m0 + half * 8;
            size_t orow = (Sremap > 0) ? ((size_t)(m & 31) * Sremap + (size_t)(m >> 5)) : (size_t)m;
            float* crow = C + orow * (size_t)N;
#pragma unroll
            for (int nt = 0; nt < 8; nt++) {
                int col = bn + wn + nt * 8 + tg * 2;
                float bv0 = bias ? bias[col]     : 0.f;
                float bv1 = bias ? bias[col + 1] : 0.f;
                float2 v;
                v.x = acc[mt][nt][half * 2 + 0] + bv0;
                v.y = acc[mt][nt][half * 2 + 1] + bv1;
                *(float2*)&crow[col] = v;
            }
        }
    }
}

// ================= skinny GEMM partial (decoder phases) =================
__device__ __forceinline__ void skinny64(
    const float* __restrict__ A,
    const float* __restrict__ W, int ldw,
    int cb, int kbase,
    float* __restrict__ outp, int oldd,
    float (*as)[68], float (*ws)[68])
{
    const int tid = threadIdx.x;
    const int ar = tid >> 3;
    const int ak = (tid & 7) << 3;
    const int wr = tid >> 2;
    const int wk = (tid & 3) << 4;
    const int wrx = wr ^ ((wk >> 1) & 24);
    const int ob = (tid >> 4) << 1;
    const int oc = (tid & 15) << 2;

    const float* Ap = A + (size_t)ar * Hh + kbase + ak;
    const float* Wp = W + (size_t)(cb + wr) * ldw + kbase + wk;

    float4 a0 = *(const float4*)Ap;
    float4 a1 = *(const float4*)(Ap + 4);
    float4 w0 = *(const float4*)Wp;
    float4 w1 = *(const float4*)(Wp + 4);
    float4 w2 = *(const float4*)(Wp + 8);
    float4 w3 = *(const float4*)(Wp + 12);

    float acc0[4] = {0.f, 0.f, 0.f, 0.f};
    float acc1[4] = {0.f, 0.f, 0.f, 0.f};

    for (int k0 = 0; k0 < 512; k0 += 64) {
        __syncthreads();
        *(float4*)&as[ar][ak]     = a0;
        *(float4*)&as[ar][ak + 4] = a1;
        ws[wk +  0][wrx] = w0.x; ws[wk +  1][wrx] = w0.y; ws[wk +  2][wrx] = w0.z; ws[wk +  3][wrx] = w0.w;
        ws[wk +  4][wrx] = w1.x; ws[wk +  5][wrx] = w1.y; ws[wk +  6][wrx] = w1.z; ws[wk +  7][wrx] = w1.w;
        ws[wk +  8][wrx] = w2.x; ws[wk +  9][wrx] = w2.y; ws[wk + 10][wrx] = w2.z; ws[wk + 11][wrx] = w2.w;
        ws[wk + 12][wrx] = w3.x; ws[wk + 13][wrx] = w3.y; ws[wk + 14][wrx] = w3.z; ws[wk + 15][wrx] = w3.w;
        __syncthreads();
        if (k0 + 64 < 512) {
            a0 = *(const float4*)(Ap + k0 + 64);
            a1 = *(const float4*)(Ap + k0 + 68);
            w0 = *(const float4*)(Wp + k0 + 64);
            w1 = *(const float4*)(Wp + k0 + 68);
            w2 = *(const float4*)(Wp + k0 + 72);
            w3 = *(const float4*)(Wp + k0 + 76);
        }
#pragma unroll 16
        for (int kk = 0; kk < 64; kk++) {
            float4 w4 = *(const float4*)&ws[kk][oc ^ ((kk >> 1) & 24)];
            float aa = as[ob][kk];
            float ab = as[ob + 1][kk];
            acc0[0] += aa * w4.x; acc0[1] += aa * w4.y; acc0[2] += aa * w4.z; acc0[3] += aa * w4.w;
            acc1[0] += ab * w4.x; acc1[1] += ab * w4.y; acc1[2] += ab * w4.z; acc1[3] += ab * w4.w;
        }
    }

    float* o0 = outp + (size_t)ob * oldd + cb + oc;
    *(float4*)o0 = make_float4(acc0[0], acc0[1], acc0[2], acc0[3]);
    *(float4*)(o0 + oldd) = make_float4(acc1[0], acc1[1], acc1[2], acc1[3]);
}

// ================= persistent encoder: fused, 1 barrier/step, W in smem =================
// 128 blocks; block owns 8 gate-indices j (j0=bid*8). Whh rows {j, 1024+j, 2048+j}
// transposed into smem once (wt[k][j*3+g], row stride 25). Per step: stage h in
// 128-k chunks (register-prefetched), accumulate r/z/n, apply gate, write h_next.
__global__ void __launch_bounds__(256) enc_persistent(
    const float* __restrict__ Whh, const float* __restrict__ bhh,
    const int* __restrict__ enclen)
{
    extern __shared__ float dyn[];
    float* wt = dyn;              // [1024][25]
    float* hs = dyn + 1024 * 25;  // [32][132]
    __shared__ unsigned s_base;
    int tid = threadIdx.x, bid = blockIdx.x;
    if (tid == 0) s_base = *(volatile unsigned*)&g_bar_sense;

    int j0 = bid * 8;
#pragma unroll 1
    for (int r = 0; r < 24; r++) {
        int g = r >> 3, j = r & 7;
        const float* wrow = Whh + (size_t)(g * 1024 + j0 + j) * 1024;
        for (int k = tid; k < 1024; k += 256)
            wt[k * 25 + j * 3 + g] = wrow[k];
    }
    __syncthreads();
    unsigned ep = s_base;

    int b  = tid >> 3;          // 0..31
    int jj = tid & 7;           // 0..7
    int jg = j0 + jj;
    float br = bhh[jg], bz = bhh[1024 + jg], bn_ = bhh[2048 + jg];
    int len = enclen[b];

    int lb = tid >> 3;          // stage-load batch
    int lk = (tid & 7) << 4;    // stage-load k offset

    for (int t = 0; t < SEe; t++) {
        const float* h  = (t & 1) ? g_h1 : g_h0;
        float*       hn = (t & 1) ? g_h0 : g_h1;

        float accr = br, accz = bz, accn = bn_;
        const float* hrow = h + (size_t)lb * 1024;
        float4 p0 = *(const float4*)(hrow + lk);
        float4 p1 = *(const float4*)(hrow + lk + 4);
        float4 p2 = *(const float4*)(hrow + lk + 8);
        float4 p3 = *(const float4*)(hrow + lk + 12);

        const float* hb = hs + b * 132;
#pragma unroll 1
        for (int c = 0; c < 8; c++) {
            __syncthreads();
            float* hd = hs + lb * 132 + lk;
            *(float4*)(hd)      = p0;
            *(float4*)(hd + 4)  = p1;
            *(float4*)(hd + 8)  = p2;
            *(float4*)(hd + 12) = p3;
            __syncthreads();
            if (c < 7) {
                const float* src = hrow + (c + 1) * 128 + lk;
                p0 = *(const float4*)(src);
                p1 = *(const float4*)(src + 4);
                p2 = *(const float4*)(src + 8);
                p3 = *(const float4*)(src + 12);
            }
            const float* wb = wt + (size_t)(c * 128) * 25 + jj * 3;
#pragma unroll 8
            for (int kk = 0; kk < 128; kk++) {
                float a = hb[kk];
                accr += a * wb[kk * 25 + 0];
                accz += a * wb[kk * 25 + 1];
                accn += a * wb[kk * 25 + 2];
            }
        }

        const float* gi = g_enc_gi + ((size_t)t * Bb + b) * G3;
        float r = sigf(gi[jg] + accr);
        float z = sigf(gi[1024 + jg] + accz);
        float n = tanhf(gi[2048 + jg] + r * accn);
        float hold = h[b * 1024 + jg];
        float hnv = (1.f - z) * n + z * hold;
        bool msk = t < len;
        hn[b * 1024 + jg] = msk ? hnv : hold;
        g_enc_out[(size_t)t * Bb * Hh + b * 1024 + jg] = msk ? hnv : 0.f;
        grid_bar(++ep, NBE);
    }
}

// ================= persistent decoder (R7 structure) =================
__global__ void __launch_bounds__(256) dec_persistent(
    const float* __restrict__ qW, const float* __restrict__ qb,
    const float* __restrict__ Whh, const float* __restrict__ Wih,
    const float* __restrict__ bhh)
{
    __shared__ unsigned s_base;
    __shared__ __align__(16) float as[32][68];
    __shared__ __align__(16) float ws[64][68];
    __shared__ __align__(16) float qs[Hh];
    __shared__ float sc[SEe];
    __shared__ float red[8];
    int tid = threadIdx.x, bid = blockIdx.x, lane = tid & 31, warp = tid >> 5;
    if (tid == 0) s_base = *(volatile unsigned*)&g_bar_sense;
    __syncthreads();
    unsigned ep = s_base;

    const float* Wc = Wih + Ee;

    for (int t = 0; t < SDd; t++) {
        const float* h  = (t & 1) ? g_h1 : g_h0;
        float*       hn = (t & 1) ? g_h0 : g_h1;

        // A1: q partials (blocks 0..31) || gh cols 0..2047 partials (32..95)
        if (bid < 32) {
            skinny64(h, qW, Hh, (bid >> 1) * 64, (bid & 1) * 512,
                     g_qp + (size_t)(bid & 1) * (Bb * Hh), Hh, as, ws);
        } else {
            int tt = bid - 32;
            skinny64(h, Whh, Hh, (tt >> 1) * 64, (tt & 1) * 512,
                     g_ghp + (size_t)(tt & 1) * (Bb * G3), G3, as, ws);
        }
        grid_bar(++ep, NBLK);

        // A2: scores, 3 blocks per batch, q folded into smem
        {
            int b = bid & 31, part = bid >> 5;
            const float* q0 = g_qp + (size_t)b * Hh;
            const float* q1 = g_qp + (size_t)(Bb * Hh) + (size_t)b * Hh;
            for (int j = tid; j < Hh; j += 256) qs[j] = q0[j] + q1[j] + qb[j];
            __syncthreads();
            int ss = part * 86;
            int se = ss + 86; if (se > SEe) se = SEe;
            const float4* qr = (const float4*)qs;
            for (int s = ss + warp; s < se; s += 8) {
                const float4* kr = (const float4*)(g_kT + ((size_t)b * SEe + s) * Hh);
                float a = 0.f;
#pragma unroll
                for (int i = 0; i < 8; i++) {
                    float4 kv = kr[lane + 32 * i];
                    float4 qv = qr[lane + 32 * i];
                    a += kv.x * qv.x + kv.y * qv.y + kv.z * qv.z + kv.w * qv.w;
                }
#pragma unroll
                for (int o = 16; o > 0; o >>= 1) a += __shfl_xor_sync(0xffffffffu, a, o);
                if (lane == 0) g_sc[b * SEe + s] = a;
            }
        }
        grid_bar(++ep, NBLK);

        // A3: softmax + ctx halves (blocks 0..63) || gh cols 2048..3071 (64..95)
        if (bid < 64) {
            int b = bid >> 1, half = bid & 1;
            float v = g_sc[b * SEe + tid];
            float m = v;
#pragma unroll
            for (int o = 16; o > 0; o >>= 1) m = fmaxf(m, __shfl_xor_sync(0xffffffffu, m, o));
            if (lane == 0) red[warp] = m;
            __syncthreads();
            float mm = red[0];
#pragma unroll
            for (int i = 1; i < 8; i++) mm = fmaxf(mm, red[i]);
            float e = expf(v - mm);
            float ssum = e;
#pragma unroll
            for (int o = 16; o > 0; o >>= 1) ssum += __shfl_xor_sync(0xffffffffu, ssum, o);
            __syncthreads();
            if (lane == 0) red[warp] = ssum;
            __syncthreads();
            float tot = 0.f;
#pragma unroll
            for (int i = 0; i < 8; i++) tot += red[i];
            sc[tid] = e / tot;
            __syncthreads();

            int c0 = half * 512 + tid;
            float s0 = 0.f, s1 = 0.f;
#pragma unroll 8
            for (int s = 0; s < SEe; s++) {
                float a = sc[s];
                const float* er = g_enc_out + ((size_t)s * Bb + b) * Hh;
                s0 += a * er[c0];
                s1 += a * er[c0 + 256];
            }
            g_ctx[(size_t)b * Hh + c0]       = s0;
            g_ctx[(size_t)b * Hh + c0 + 256] = s1;
        } else {
            int tt = bid - 64;
            skinny64(h, Whh, Hh, 2048 + (tt >> 1) * 64, (tt & 1) * 512,
                     g_ghp + (size_t)(tt & 1) * (Bb * G3), G3, as, ws);
        }
        grid_bar(++ep, NBLK);

        // A4: gc = ctx @ Wc.T partials
        skinny64(g_ctx, Wc, Ee + Hh, (bid >> 1) * 64, (bid & 1) * 512,
                 g_gcp + (size_t)(bid & 1) * (Bb * G3), G3, as, ws);
        grid_bar(++ep, NBLK);

        // A5: gate + state update
        for (int idx = bid * 256 + tid; idx < Bb * Hh; idx += NBLK * 256) {
            int b = idx >> 10, j = idx & 1023;
            const float* gx  = g_dec_gx + (size_t)(t * Bb + b) * G3;
            const float* gh0 = g_ghp + (size_t)b * G3;
            const float* gh1 = g_ghp + (size_t)(Bb * G3) + (size_t)b * G3;
            const float* gc0 = g_gcp + (size_t)b * G3;
            const float* gc1 = g_gcp + (size_t)(Bb * G3) + (size_t)b * G3;
            float hr = gh0[j]        + gh1[j]        + bhh[j];
            float hz = gh0[Hh + j]   + gh1[Hh + j]   + bhh[Hh + j];
            float hv = gh0[2*Hh + j] + gh1[2*Hh + j] + bhh[2*Hh + j];
            float ir = gx[j]        + gc0[j]        + gc1[j];
            float iz = gx[Hh + j]   + gc0[Hh + j]   + gc1[Hh + j];
            float in = gx[2*Hh + j] + gc0[2*Hh + j] + gc1[2*Hh + j];
            float r = sigf(ir + hr);
            float z = sigf(iz + hz);
            float n = tanhf(in + r * hv);
            float hold = h[idx];
            float h2 = (1.f - z) * n + z * hold;
            hn[idx] = h2;
            g_dec_out[(size_t)t * Bb * Hh + idx] = h2;
        }
        grid_bar(++ep, NBLK);
    }
}

extern "C" void kernel_launch(void* const* d_in, const int* in_sizes, int n_in,
                              void* d_out, int out_size)
{
    const int*   enc_in   = (const int*)d_in[0];
    const int*   dec_in   = (const int*)d_in[1];
    const int*   enc_len  = (const int*)d_in[2];
    const float* emb      = (const float*)d_in[4];
    const float* enc_Wih  = (const float*)d_in[5];
    const float* enc_Whh  = (const float*)d_in[6];
    const float* enc_bih  = (const float*)d_in[7];
    const float* enc_bhh  = (const float*)d_in[8];
    const float* dec_Wih  = (const float*)d_in[9];
    const float* dec_Whh  = (const float*)d_in[10];
    const float* dec_bih  = (const float*)d_in[11];
    const float* dec_bhh  = (const float*)d_in[12];
    const float* attn_kW  = (const float*)d_in[13];
    const float* attn_kb  = (const float*)d_in[14];
    const float* attn_qW  = (const float*)d_in[15];
    const float* attn_qb  = (const float*)d_in[16];
    const float* logits_W = (const float*)d_in[17];
    const float* logits_b = (const float*)d_in[18];
    float* out = (float*)d_out;
    (void)in_sizes; (void)n_in; (void)out_size;

    float *p_enc_gi, *p_dec_gx, *p_enc_out, *p_kT, *p_dec_out;
    int *p_enc_rows, *p_dec_rows;
    cudaGetSymbolAddress((void**)&p_enc_gi,  g_enc_gi);
    cudaGetSymbolAddress((void**)&p_dec_gx,  g_dec_gx);
    cudaGetSymbolAddress((void**)&p_enc_out, g_enc_out);
    cudaGetSymbolAddress((void**)&p_kT,      g_kT);
    cudaGetSymbolAddress((void**)&p_dec_out, g_dec_out);
    cudaGetSymbolAddress((void**)&p_enc_rows, g_enc_rows);
    cudaGetSymbolAddress((void**)&p_dec_rows, g_dec_rows);

    const int enc_smem = (1024 * 25 + 32 * 132) * 4;   // 119,296 B
    cudaFuncSetAttribute(enc_persistent,
                         cudaFuncAttributeMaxDynamicSharedMemorySize, enc_smem);

    build_rows_kernel<<<32, 256>>>(enc_in, dec_in);
    init_h_kernel<<<(Bb * Hh) / 256, 256>>>();

    // encoder input projection, then encoder (moved up so ncu's capture slot
    // lands on enc_persistent instead of the dec_gx GEMM)
    gemm_tf32<<<dim3(G3 / 128, (SEe * Bb) / 128), 256>>>(
        emb, p_enc_rows, Ee, enc_Wih, Ee, enc_bih, p_enc_gi, G3, Ee, 0);

    enc_persistent<<<NBE, 256, enc_smem>>>(enc_Whh, enc_bhh, enc_len);

    // attention keys
    gemm_tf32<<<dim3(Hh / 128, (SEe * Bb) / 128), 256>>>(
        p_enc_out, nullptr, Hh, attn_kW, Hh, attn_kb, p_kT, Hh, Hh, SEe);

    // decoder input projection (x part), then decoder
    gemm_tf32<<<dim3(G3 / 128, (SDd * Bb) / 128), 256>>>(
        emb, p_dec_rows, Ee, dec_Wih, Ee + Hh, dec_bih, p_dec_gx, G3, Ee, 0);

    dec_persistent<<<NBLK, 256>>>(attn_qW, attn_qb, dec_Whh, dec_Wih, dec_bhh);

    // logits
    gemm_tf32<<<dim3(Vv / 128, (SDd * Bb) / 128), 256>>>(
        p_dec_out, nullptr, Hh, logits_W, Hh, logits_b, out, Vv, Hh, SDd);
}

// round 13
// speedup vs baseline: 1.6742x; 1.1304x over previous
#include <cuda_runtime.h>
#include <cstdint>
#include <cstddef>

#define Vv   32000
#define Ee   1024
#define Hh   1024
#define Bb   32
#define SEe  256
#define SDd  128
#define G3   3072
#define NBE  128
#define NBD  128

__device__ float g_enc_gi[(size_t)SEe * Bb * G3];
__device__ float g_dec_gx[(size_t)SDd * Bb * G3];
__device__ float g_enc_out[(size_t)SEe * Bb * Hh];
__device__ float g_kT[(size_t)Bb * SEe * Hh];
__device__ float g_Mk[(size_t)Bb * SEe * Hh];
__device__ float g_qWT[(size_t)Hh * Hh];
__device__ float g_sb0[Bb * SEe];
__device__ float g_dec_out[(size_t)SDd * Bb * Hh];
__device__ float g_h0[Bb * Hh];
__device__ float g_h1[Bb * Hh];
__device__ float g_ctx[Bb * Hh];
__device__ float g_sc[Bb * SEe];
__device__ int   g_enc_rows[SEe * Bb];
__device__ int   g_dec_rows[SDd * Bb];
__device__ unsigned g_bar_count;
__device__ unsigned g_bar_sense;

__device__ __forceinline__ float sigf(float x) { return 1.f / (1.f + expf(-x)); }

// software grid barrier, nanosleep spin (tight spin regressed via DVFS clock drop)
__device__ __forceinline__ void grid_bar(unsigned target, unsigned nblk)
{
    __syncthreads();
    if (threadIdx.x == 0) {
        __threadfence();
        if (atomicAdd(&g_bar_count, 1u) == nblk - 1) {
            atomicExch(&g_bar_count, 0u);
            __threadfence();
            atomicExch(&g_bar_sense, target);
        } else {
            while (*(volatile unsigned*)&g_bar_sense < target) __nanosleep(64);
            __threadfence();
        }
    }
    __syncthreads();
}

__global__ void __launch_bounds__(256) build_rows_kernel(
    const int* __restrict__ enc_in, const int* __restrict__ dec_in)
{
    int m = blockIdx.x * 256 + threadIdx.x;
    if (m < SEe * Bb) {
        int t = m >> 5, b = m & 31;
        g_enc_rows[m] = enc_in[b * SEe + t];
    }
    if (m < SDd * Bb) {
        int t = m >> 5, b = m & 31;
        g_dec_rows[m] = dec_in[b * SDd + t];
    }
}

__global__ void __launch_bounds__(256) init_h_kernel()
{
    int i = blockIdx.x * 256 + threadIdx.x;
    if (i < Bb * Hh) g_h0[i] = 0.f;
}

// transpose qW (1024x1024) -> g_qWT
__global__ void __launch_bounds__(256) transpose_qw(const float* __restrict__ qW)
{
    __shared__ float tile[32][33];
    int bx = blockIdx.x * 32, by = blockIdx.y * 32;
    int tx = threadIdx.x & 31, ty = threadIdx.x >> 5;
#pragma unroll
    for (int i = 0; i < 32; i += 8)
        tile[ty + i][tx] = qW[(size_t)(by + ty + i) * Hh + bx + tx];
    __syncthreads();
#pragma unroll
    for (int i = 0; i < 32; i += 8)
        g_qWT[(size_t)(bx + ty + i) * Hh + by + tx] = tile[tx][ty + i];
}

// sb0[m] = kT[m,:] . qb
__global__ void __launch_bounds__(256) sb0_kernel(const float* __restrict__ qb)
{
    int m = blockIdx.x * 8 + (threadIdx.x >> 5);
    int lane = threadIdx.x & 31;
    const float4* kr = (const float4*)(g_kT + (size_t)m * Hh);
    const float4* qr = (const float4*)qb;
    float a = 0.f;
#pragma unroll
    for (int i = 0; i < 8; i++) {
        float4 kv = kr[lane + 32 * i];
        float4 qv = qr[lane + 32 * i];
        a += kv.x * qv.x + kv.y * qv.y + kv.z * qv.z + kv.w * qv.w;
    }
#pragma unroll
    for (int o = 16; o > 0; o >>= 1) a += __shfl_xor_sync(0xffffffffu, a, o);
    if (lane == 0) g_sb0[m] = a;
}

// ================= tf32 tensor-core GEMM =================
__device__ __forceinline__ float to_tf32(float x)
{
    uint32_t u;
    asm("cvt.rna.tf32.f32 %0, %1;" : "=r"(u) : "f"(x));
    return __uint_as_float(u);
}

__device__ __forceinline__ float4 cvt4(float4 v)
{
    float4 r;
    r.x = to_tf32(v.x); r.y = to_tf32(v.y); r.z = to_tf32(v.z); r.w = to_tf32(v.w);
    return r;
}

__device__ __forceinline__ void mma_tf32(float* c, const float* a, const float* b)
{
    asm volatile(
        "mma.sync.aligned.m16n8k8.row.col.f32.tf32.tf32.f32 "
        "{%0,%1,%2,%3}, {%4,%5,%6,%7}, {%8,%9}, {%0,%1,%2,%3};"
        : "+f"(c[0]), "+f"(c[1]), "+f"(c[2]), "+f"(c[3])
        : "r"(__float_as_uint(a[0])), "r"(__float_as_uint(a[1])),
          "r"(__float_as_uint(a[2])), "r"(__float_as_uint(a[3])),
          "r"(__float_as_uint(b[0])), "r"(__float_as_uint(b[1])));
}

__global__ void __launch_bounds__(256) gemm_tf32(
    const float* __restrict__ A, const int* __restrict__ arows, int lda,
    const float* __restrict__ W, int ldw,
    const float* __restrict__ bias,
    float* __restrict__ C, int N, int K, int Sremap)
{
    __shared__ __align__(16) float As[2][128][20];
    __shared__ __align__(16) float Bs[2][128][20];

    int tid = threadIdx.x;
    int bm = blockIdx.y * 128, bn = blockIdx.x * 128;
    int lr = tid >> 2;
    int lk = (tid & 3) << 2;

    int ar0 = arows ? arows[bm + lr] : bm + lr;
    int ar1 = arows ? arows[bm + lr + 64] : bm + lr + 64;
    const float* arow0 = A + (size_t)ar0 * lda + lk;
    const float* arow1 = A + (size_t)ar1 * lda + lk;
    const float* wrow0 = W + (size_t)(bn + lr) * ldw + lk;
    const float* wrow1 = W + (size_t)(bn + lr + 64) * ldw + lk;

    int warp = tid >> 5, lane = tid & 31;
    int wm = (warp >> 1) * 32, wn = (warp & 1) * 64;
    int g = lane >> 2, tg = lane & 3;

    float acc[2][8][4];
#pragma unroll
    for (int mt = 0; mt < 2; mt++)
#pragma unroll
        for (int nt = 0; nt < 8; nt++)
#pragma unroll
            for (int i = 0; i < 4; i++) acc[mt][nt][i] = 0.f;

    float4 a0 = *(const float4*)arow0;
    float4 a1 = *(const float4*)arow1;
    float4 b0 = *(const float4*)wrow0;
    float4 b1 = *(const float4*)wrow1;

    int buf = 0;
    for (int k0 = 0; k0 < K; k0 += 16) {
        *(float4*)&As[buf][lr][lk]      = cvt4(a0);
        *(float4*)&As[buf][lr + 64][lk] = cvt4(a1);
        *(float4*)&Bs[buf][lr][lk]      = cvt4(b0);
        *(float4*)&Bs[buf][lr + 64][lk] = cvt4(b1);
        __syncthreads();
        if (k0 + 16 < K) {
            a0 = *(const float4*)(arow0 + k0 + 16);
            a1 = *(const float4*)(arow1 + k0 + 16);
            b0 = *(const float4*)(wrow0 + k0 + 16);
            b1 = *(const float4*)(wrow1 + k0 + 16);
        }
#pragma unroll
        for (int ks = 0; ks < 2; ks++) {
            float af[2][4], bf[8][2];
#pragma unroll
            for (int mt = 0; mt < 2; mt++) {
                const float* p0 = &As[buf][wm + mt * 16 + g][ks * 8 + tg];
                const float* p1 = &As[buf][wm + mt * 16 + g + 8][ks * 8 + tg];
                af[mt][0] = p0[0]; af[mt][1] = p1[0];
                af[mt][2] = p0[4]; af[mt][3] = p1[4];
            }
#pragma unroll
            for (int nt = 0; nt < 8; nt++) {
                const float* p = &Bs[buf][wn + nt * 8 + g][ks * 8 + tg];
                bf[nt][0] = p[0]; bf[nt][1] = p[4];
            }
#pragma unroll
            for (int mt = 0; mt < 2; mt++)
#pragma unroll
                for (int nt = 0; nt < 8; nt++)
                    mma_tf32(acc[mt][nt], af[mt], bf[nt]);
        }
        buf ^= 1;
    }

#pragma unroll
    for (int mt = 0; mt < 2; mt++) {
        int m0 = bm + wm + mt * 16 + g;
#pragma unroll
        for (int half = 0; half < 2; half++) {
            int m = m0 + half * 8;
            size_t orow = (Sremap > 0) ? ((size_t)(m & 31) * Sremap + (size_t)(m >> 5)) : (size_t)m;
            float* crow = C + orow * (size_t)N;
#pragma unroll
            for (int nt = 0; nt < 8; nt++) {
                int col = bn + wn + nt * 8 + tg * 2;
                float bv0 = bias ? bias[col]     : 0.f;
                float bv1 = bias ? bias[col + 1] : 0.f;
                float2 v;
                v.x = acc[mt][nt][half * 2 + 0] + bv0;
                v.y = acc[mt][nt][half * 2 + 1] + bv1;
                *(float2*)&crow[col] = v;
            }
        }
    }
}

// ================= persistent encoder (unchanged from R10) =================
__global__ void __launch_bounds__(256) enc_persistent(
    const float* __restrict__ Whh, const float* __restrict__ bhh,
    const int* __restrict__ enclen)
{
    extern __shared__ float dyn[];
    float* wt = dyn;              // [1024][25]
    float* hs = dyn + 1024 * 25;  // [32][132]
    __shared__ unsigned s_base;
    int tid = threadIdx.x, bid = blockIdx.x;
    if (tid == 0) s_base = *(volatile unsigned*)&g_bar_sense;

    int j0 = bid * 8;
#pragma unroll 1
    for (int r = 0; r < 24; r++) {
        int g = r >> 3, j = r & 7;
        const float* wrow = Whh + (size_t)(g * 1024 + j0 + j) * 1024;
        for (int k = tid; k < 1024; k += 256)
            wt[k * 25 + j * 3 + g] = wrow[k];
    }
    __syncthreads();
    unsigned ep = s_base;

    int b  = tid >> 3;
    int jj = tid & 7;
    int jg = j0 + jj;
    float br = bhh[jg], bz = bhh[1024 + jg], bn_ = bhh[2048 + jg];
    int len = enclen[b];

    int lb = tid >> 3;
    int lk = (tid & 7) << 4;

    for (int t = 0; t < SEe; t++) {
        const float* h  = (t & 1) ? g_h1 : g_h0;
        float*       hn = (t & 1) ? g_h0 : g_h1;

        float accr = br, accz = bz, accn = bn_;
        const float* hrow = h + (size_t)lb * 1024;
        float4 p0 = *(const float4*)(hrow + lk);
        float4 p1 = *(const float4*)(hrow + lk + 4);
        float4 p2 = *(const float4*)(hrow + lk + 8);
        float4 p3 = *(const float4*)(hrow + lk + 12);

        const float* hb = hs + b * 132;
#pragma unroll 1
        for (int c = 0; c < 8; c++) {
            __syncthreads();
            float* hd = hs + lb * 132 + lk;
            *(float4*)(hd)      = p0;
            *(float4*)(hd + 4)  = p1;
            *(float4*)(hd + 8)  = p2;
            *(float4*)(hd + 12) = p3;
            __syncthreads();
            if (c < 7) {
                const float* src = hrow + (c + 1) * 128 + lk;
                p0 = *(const float4*)(src);
                p1 = *(const float4*)(src + 4);
                p2 = *(const float4*)(src + 8);
                p3 = *(const float4*)(src + 12);
            }
            const float* wb = wt + (size_t)(c * 128) * 25 + jj * 3;
#pragma unroll 8
            for (int kk = 0; kk < 128; kk++) {
                float a = hb[kk];
                accr += a * wb[kk * 25 + 0];
                accz += a * wb[kk * 25 + 1];
                accn += a * wb[kk * 25 + 2];
            }
        }

        const float* gi = g_enc_gi + ((size_t)t * Bb + b) * G3;
        float r = sigf(gi[jg] + accr);
        float z = sigf(gi[1024 + jg] + accz);
        float n = tanhf(gi[2048 + jg] + r * accn);
        float hold = h[b * 1024 + jg];
        float hnv = (1.f - z) * n + z * hold;
        bool msk = t < len;
        hn[b * 1024 + jg] = msk ? hnv : hold;
        g_enc_out[(size_t)t * Bb * Hh + b * 1024 + jg] = msk ? hnv : 0.f;
        grid_bar(++ep, NBE);
    }
}

// ===== fused accumulation pass: acc{0,1,2} += sum_k src[b][k] * W{r,z,n}[jj][k] =====
// wsm: smem weight base, rows [3][8][1028]; hs: staging [32][132]
__device__ __forceinline__ void fused_pass(
    const float* __restrict__ src, const float* __restrict__ wsm,
    float* __restrict__ hs, int tid, float& A0, float& A1, float& A2)
{
    int lb = tid >> 3, lk = (tid & 7) << 4;
    int b = lb, jj = tid & 7;
    const float* srow = src + (size_t)lb * 1024 + lk;
    float4 p0 = *(const float4*)(srow);
    float4 p1 = *(const float4*)(srow + 4);
    float4 p2 = *(const float4*)(srow + 8);
    float4 p3 = *(const float4*)(srow + 12);
    const float* w0 = wsm + (size_t)jj * 1028;
    const float* w1 = wsm + (size_t)(8 + jj) * 1028;
    const float* w2 = wsm + (size_t)(16 + jj) * 1028;
    const float* hb = hs + b * 132;
#pragma unroll 1
    for (int c = 0; c < 8; c++) {
        __syncthreads();
        float* hd = hs + lb * 132 + lk;
        *(float4*)(hd)      = p0;
        *(float4*)(hd + 4)  = p1;
        *(float4*)(hd + 8)  = p2;
        *(float4*)(hd + 12) = p3;
        __syncthreads();
        if (c < 7) {
            const float* s2 = srow + (c + 1) * 128;
            p0 = *(const float4*)(s2);
            p1 = *(const float4*)(s2 + 4);
            p2 = *(const float4*)(s2 + 8);
            p3 = *(const float4*)(s2 + 12);
        }
        const float* wr = w0 + c * 128;
        const float* wz = w1 + c * 128;
        const float* wn = w2 + c * 128;
#pragma unroll 8
        for (int kk = 0; kk < 128; kk += 4) {
            float4 a4 = *(const float4*)(hb + kk);
            float4 r4 = *(const float4*)(wr + kk);
            float4 z4 = *(const float4*)(wz + kk);
            float4 n4 = *(const float4*)(wn + kk);
            A0 += a4.x * r4.x + a4.y * r4.y + a4.z * r4.z + a4.w * r4.w;
            A1 += a4.x * z4.x + a4.y * z4.y + a4.z * z4.z + a4.w * z4.w;
            A2 += a4.x * n4.x + a4.y * n4.y + a4.z * n4.z + a4.w * n4.w;
        }
    }
}

// ================= persistent decoder: 3 barriers/step, W-resident =================
__global__ void __launch_bounds__(256) dec_persistent(
    const float* __restrict__ Whh, const float* __restrict__ Wih,
    const float* __restrict__ bhh)
{
    extern __shared__ float dyn[];
    float* wh = dyn;                        // [3][8][1028]
    float* wc = dyn + 3 * 8 * 1028;         // [3][8][1028]
    float* hs = dyn + 6 * 8 * 1028;         // [32][132] staging (also P1 h cache)
    __shared__ float sc[SEe];
    __shared__ float red[8];
    __shared__ unsigned s_base;
    int tid = threadIdx.x, bid = blockIdx.x, lane = tid & 31, warp = tid >> 5;
    if (tid == 0) s_base = *(volatile unsigned*)&g_bar_sense;

    const float* Wc = Wih + Ee;             // ctx cols of dec_Wih, row stride 2048
    int j0 = bid * 8;
#pragma unroll 1
    for (int r = 0; r < 24; r++) {
        int g = r >> 3, jj = r & 7;
        const float4* s1 = (const float4*)(Whh + (size_t)(g * 1024 + j0 + jj) * 1024);
        float4* d1 = (float4*)(wh + (size_t)(g * 8 + jj) * 1028);
        d1[tid] = s1[tid];
        const float4* s2 = (const float4*)(Wc + (size_t)(g * 1024 + j0 + jj) * 2048);
        float4* d2 = (float4*)(wc + (size_t)(g * 8 + jj) * 1028);
        d2[tid] = s2[tid];
    }
    __syncthreads();
    unsigned ep = s_base;

    int b  = tid >> 3;
    int jj = tid & 7;
    int jg = j0 + jj;
    float br = bhh[jg], bz = bhh[1024 + jg], bn_ = bhh[2048 + jg];

    int pb = bid >> 2;          // batch owned for P1/P2 (4 blocks per batch)
    int quarter = bid & 3;

    for (int t = 0; t < SDd; t++) {
        const float* h  = (t & 1) ? g_h1 : g_h0;
        float*       hn = (t & 1) ? g_h0 : g_h1;

        // ---- P1: scores[pb][s] = Mk[pb,s,:] . h[pb] + sb0 ; 64 s per block ----
        {
            ((float4*)hs)[tid] = ((const float4*)(h + (size_t)pb * 1024))[tid];
            __syncthreads();
            const float4* hv = (const float4*)hs;
            int s0 = quarter * 64;
            for (int s = s0 + warp; s < s0 + 64; s += 8) {
                int m = pb * 256 + s;
                const float4* mk = (const float4*)(g_Mk + (size_t)m * 1024);
                float a = 0.f;
#pragma unroll
                for (int i = 0; i < 8; i++) {
                    float4 kv = mk[lane + 32 * i];
                    float4 qv = hv[lane + 32 * i];
                    a += kv.x * qv.x + kv.y * qv.y + kv.z * qv.z + kv.w * qv.w;
                }
#pragma unroll
                for (int o = 16; o > 0; o >>= 1) a += __shfl_xor_sync(0xffffffffu, a, o);
                if (lane == 0) g_sc[m] = a + g_sb0[m];
            }
        }
        grid_bar(++ep, NBD);

        // ---- P2: softmax (redundant per block) + ctx quarter ----
        {
            float v = g_sc[pb * 256 + tid];
            float m = v;
#pragma unroll
            for (int o = 16; o > 0; o >>= 1) m = fmaxf(m, __shfl_xor_sync(0xffffffffu, m, o));
            if (lane == 0) red[warp] = m;
            __syncthreads();
            float mm = red[0];
#pragma unroll
            for (int i = 1; i < 8; i++) mm = fmaxf(mm, red[i]);
            float e = expf(v - mm);
            float ssum = e;
#pragma unroll
            for (int o = 16; o > 0; o >>= 1) ssum += __shfl_xor_sync(0xffffffffu, ssum, o);
            __syncthreads();
            if (lane == 0) red[warp] = ssum;
            __syncthreads();
            float tot = 0.f;
#pragma unroll
            for (int i = 0; i < 8; i++) tot += red[i];
            sc[tid] = e / tot;
            __syncthreads();

            int c0 = quarter * 256 + tid;
            float s0 = 0.f;
#pragma unroll 8
            for (int s = 0; s < SEe; s++)
                s0 += sc[s] * g_enc_out[(size_t)s * Bb * Hh + pb * 1024 + c0];
            g_ctx[(size_t)pb * 1024 + c0] = s0;
        }
        grid_bar(++ep, NBD);

        // ---- P3: fused gh + gc + gate ----
        {
            float ar_ = br, az = bz, an = bn_;
            float cr = 0.f, cz = 0.f, cn = 0.f;
            fused_pass(h,     wh, hs, tid, ar_, az, an);
            fused_pass(g_ctx, wc, hs, tid, cr,  cz, cn);

            const float* gx = g_dec_gx + ((size_t)t * Bb + b) * G3;
            float r = sigf(gx[jg] + cr + ar_);
            float z = sigf(gx[1024 + jg] + cz + az);
            float n = tanhf(gx[2048 + jg] + cn + r * an);
            float hold = h[b * 1024 + jg];
            float h2 = (1.f - z) * n + z * hold;
            hn[b * 1024 + jg] = h2;
            g_dec_out[(size_t)t * Bb * Hh + b * 1024 + jg] = h2;
        }
        grid_bar(++ep, NBD);
    }
}

extern "C" void kernel_launch(void* const* d_in, const int* in_sizes, int n_in,
                              void* d_out, int out_size)
{
    const int*   enc_in   = (const int*)d_in[0];
    const int*   dec_in   = (const int*)d_in[1];
    const int*   enc_len  = (const int*)d_in[2];
    const float* emb      = (const float*)d_in[4];
    const float* enc_Wih  = (const float*)d_in[5];
    const float* enc_Whh  = (const float*)d_in[6];
    const float* enc_bih  = (const float*)d_in[7];
    const float* enc_bhh  = (const float*)d_in[8];
    const float* dec_Wih  = (const float*)d_in[9];
    const float* dec_Whh  = (const float*)d_in[10];
    const float* dec_bih  = (const float*)d_in[11];
    const float* dec_bhh  = (const float*)d_in[12];
    const float* attn_kW  = (const float*)d_in[13];
    const float* attn_kb  = (const float*)d_in[14];
    const float* attn_qW  = (const float*)d_in[15];
    const float* attn_qb  = (const float*)d_in[16];
    const float* logits_W = (const float*)d_in[17];
    const float* logits_b = (const float*)d_in[18];
    float* out = (float*)d_out;
    (void)in_sizes; (void)n_in; (void)out_size;

    float *p_enc_gi, *p_dec_gx, *p_enc_out, *p_kT, *p_Mk, *p_qWT, *p_dec_out;
    int *p_enc_rows, *p_dec_rows;
    cudaGetSymbolAddress((void**)&p_enc_gi,  g_enc_gi);
    cudaGetSymbolAddress((void**)&p_dec_gx,  g_dec_gx);
    cudaGetSymbolAddress((void**)&p_enc_out, g_enc_out);
    cudaGetSymbolAddress((void**)&p_kT,      g_kT);
    cudaGetSymbolAddress((void**)&p_Mk,      g_Mk);
    cudaGetSymbolAddress((void**)&p_qWT,     g_qWT);
    cudaGetSymbolAddress((void**)&p_dec_out, g_dec_out);
    cudaGetSymbolAddress((void**)&p_enc_rows, g_enc_rows);
    cudaGetSymbolAddress((void**)&p_dec_rows, g_dec_rows);

    const int enc_smem = (1024 * 25 + 32 * 132) * 4;          // 119,296 B
    const int dec_smem = (6 * 8 * 1028 + 32 * 132) * 4;       // 214,272 B
    cudaFuncSetAttribute(enc_persistent,
                         cudaFuncAttributeMaxDynamicSharedMemorySize, enc_smem);
    cudaFuncSetAttribute(dec_persistent,
                         cudaFuncAttributeMaxDynamicSharedMemorySize, dec_smem);

    build_rows_kernel<<<32, 256>>>(enc_in, dec_in);
    init_h_kernel<<<(Bb * Hh) / 256, 256>>>();

    gemm_tf32<<<dim3(G3 / 128, (SEe * Bb) / 128), 256>>>(
        emb, p_enc_rows, Ee, enc_Wih, Ee, enc_bih, p_enc_gi, G3, Ee, 0);

    enc_persistent<<<NBE, 256, enc_smem>>>(enc_Whh, enc_bhh, enc_len);

    // kT = enc_out @ kW.T + kb   (time-major -> (b,s) via Sremap)
    gemm_tf32<<<dim3(Hh / 128, (SEe * Bb) / 128), 256>>>(
        p_enc_out, nullptr, Hh, attn_kW, Hh, attn_kb, p_kT, Hh, Hh, SEe);

    // Mk = kT @ qW  (via qW transpose), sb0 = kT . qb
    transpose_qw<<<dim3(32, 32), 256>>>(attn_qW);
    gemm_tf32<<<dim3(Hh / 128, (Bb * SEe) / 128), 256>>>(
        p_kT, nullptr, Hh, p_qWT, Hh, nullptr, p_Mk, Hh, Hh, 0);
    sb0_kernel<<<(Bb * SEe) / 8, 256>>>(attn_qb);

    gemm_tf32<<<dim3(G3 / 128, (SDd * Bb) / 128), 256>>>(
        emb, p_dec_rows, Ee, dec_Wih, Ee + Hh, dec_bih, p_dec_gx, G3, Ee, 0);

    dec_persistent<<<NBD, 256, dec_smem>>>(dec_Whh, dec_Wih, dec_bhh);

    gemm_tf32<<<dim3(Vv / 128, (SDd * Bb) / 128), 256>>>(
        p_dec_out, nullptr, Hh, logits_W, Hh, logits_b, out, Vv, Hh, SDd);
}

// round 16
// speedup vs baseline: 1.9800x; 1.1826x over previous
#include <cuda_runtime.h>
#include <cstdint>
#include <cstddef>

#define Vv   32000
#define Ee   1024
#define Hh   1024
#define Bb   32
#define SEe  256
#define SDd  128
#define G3   3072
#define NBE  128
#define NBD  128

__device__ float g_enc_gi[(size_t)SEe * Bb * G3];
__device__ float g_dec_gx[(size_t)SDd * Bb * G3];
__device__ float g_enc_out[(size_t)SEe * Bb * Hh];
__device__ float g_kT[(size_t)Bb * SEe * Hh];
__device__ float g_Mk[(size_t)Bb * SEe * Hh];
__device__ float g_qWT[(size_t)Hh * Hh];
__device__ float g_sb0[Bb * SEe];
__device__ float g_dec_out[(size_t)SDd * Bb * Hh];
__device__ float g_h0[Bb * Hh];
__device__ float g_h1[Bb * Hh];
__device__ float g_ctx[Bb * Hh];
__device__ float g_sc[Bb * SEe];
__device__ int   g_enc_rows[SEe * Bb];
__device__ int   g_dec_rows[SDd * Bb];
__device__ unsigned g_bar_count;
__device__ unsigned g_bar_sense;

__device__ __forceinline__ float sigf(float x) { return 1.f / (1.f + expf(-x)); }

// software grid barrier, nanosleep spin (tight spin regressed via DVFS clock drop)
__device__ __forceinline__ void grid_bar(unsigned target, unsigned nblk)
{
    __syncthreads();
    if (threadIdx.x == 0) {
        __threadfence();
        if (atomicAdd(&g_bar_count, 1u) == nblk - 1) {
            atomicExch(&g_bar_count, 0u);
            __threadfence();
            atomicExch(&g_bar_sense, target);
        } else {
            while (*(volatile unsigned*)&g_bar_sense < target) __nanosleep(64);
            __threadfence();
        }
    }
    __syncthreads();
}

__global__ void __launch_bounds__(256) build_rows_kernel(
    const int* __restrict__ enc_in, const int* __restrict__ dec_in)
{
    int m = blockIdx.x * 256 + threadIdx.x;
    if (m < SEe * Bb) {
        int t = m >> 5, b = m & 31;
        g_enc_rows[m] = enc_in[b * SEe + t];
    }
    if (m < SDd * Bb) {
        int t = m >> 5, b = m & 31;
        g_dec_rows[m] = dec_in[b * SDd + t];
    }
}

__global__ void __launch_bounds__(256) init_h_kernel()
{
    int i = blockIdx.x * 256 + threadIdx.x;
    if (i < Bb * Hh) g_h0[i] = 0.f;
}

// transpose qW (1024x1024) -> g_qWT
__global__ void __launch_bounds__(256) transpose_qw(const float* __restrict__ qW)
{
    __shared__ float tile[32][33];
    int bx = blockIdx.x * 32, by = blockIdx.y * 32;
    int tx = threadIdx.x & 31, ty = threadIdx.x >> 5;
#pragma unroll
    for (int i = 0; i < 32; i += 8)
        tile[ty + i][tx] = qW[(size_t)(by + ty + i) * Hh + bx + tx];
    __syncthreads();
#pragma unroll
    for (int i = 0; i < 32; i += 8)
        g_qWT[(size_t)(bx + ty + i) * Hh + by + tx] = tile[tx][ty + i];
}

// sb0[m] = kT[m,:] . qb
__global__ void __launch_bounds__(256) sb0_kernel(const float* __restrict__ qb)
{
    int m = blockIdx.x * 8 + (threadIdx.x >> 5);
    int lane = threadIdx.x & 31;
    const float4* kr = (const float4*)(g_kT + (size_t)m * Hh);
    const float4* qr = (const float4*)qb;
    float a = 0.f;
#pragma unroll
    for (int i = 0; i < 8; i++) {
        float4 kv = kr[lane + 32 * i];
        float4 qv = qr[lane + 32 * i];
        a += kv.x * qv.x + kv.y * qv.y + kv.z * qv.z + kv.w * qv.w;
    }
#pragma unroll
    for (int o = 16; o > 0; o >>= 1) a += __shfl_xor_sync(0xffffffffu, a, o);
    if (lane == 0) g_sb0[m] = a;
}

// ================= tf32 tensor-core GEMM =================
__device__ __forceinline__ float to_tf32(float x)
{
    uint32_t u;
    asm("cvt.rna.tf32.f32 %0, %1;" : "=r"(u) : "f"(x));
    return __uint_as_float(u);
}

__device__ __forceinline__ float4 cvt4(float4 v)
{
    float4 r;
    r.x = to_tf32(v.x); r.y = to_tf32(v.y); r.z = to_tf32(v.z); r.w = to_tf32(v.w);
    return r;
}

__device__ __forceinline__ void mma_tf32(float* c, const float* a, const float* b)
{
    asm volatile(
        "mma.sync.aligned.m16n8k8.row.col.f32.tf32.tf32.f32 "
        "{%0,%1,%2,%3}, {%4,%5,%6,%7}, {%8,%9}, {%0,%1,%2,%3};"
        : "+f"(c[0]), "+f"(c[1]), "+f"(c[2]), "+f"(c[3])
        : "r"(__float_as_uint(a[0])), "r"(__float_as_uint(a[1])),
          "r"(__float_as_uint(a[2])), "r"(__float_as_uint(a[3])),
          "r"(__float_as_uint(b[0])), "r"(__float_as_uint(b[1])));
}

__global__ void __launch_bounds__(256) gemm_tf32(
    const float* __restrict__ A, const int* __restrict__ arows, int lda,
    const float* __restrict__ W, int ldw,
    const float* __restrict__ bias,
    float* __restrict__ C, int N, int K, int Sremap)
{
    __shared__ __align__(16) float As[2][128][20];
    __shared__ __align__(16) float Bs[2][128][20];

    int tid = threadIdx.x;
    int bm = blockIdx.y * 128, bn = blockIdx.x * 128;
    int lr = tid >> 2;
    int lk = (tid & 3) << 2;

    int ar0 = arows ? arows[bm + lr] : bm + lr;
    int ar1 = arows ? arows[bm + lr + 64] : bm + lr + 64;
    const float* arow0 = A + (size_t)ar0 * lda + lk;
    const float* arow1 = A + (size_t)ar1 * lda + lk;
    const float* wrow0 = W + (size_t)(bn + lr) * ldw + lk;
    const float* wrow1 = W + (size_t)(bn + lr + 64) * ldw + lk;

    int warp = tid >> 5, lane = tid & 31;
    int wm = (warp >> 1) * 32, wn = (warp & 1) * 64;
    int g = lane >> 2, tg = lane & 3;

    float acc[2][8][4];
#pragma unroll
    for (int mt = 0; mt < 2; mt++)
#pragma unroll
        for (int nt = 0; nt < 8; nt++)
#pragma unroll
            for (int i = 0; i < 4; i++) acc[mt][nt][i] = 0.f;

    float4 a0 = *(const float4*)arow0;
    float4 a1 = *(const float4*)arow1;
    float4 b0 = *(const float4*)wrow0;
    float4 b1 = *(const float4*)wrow1;

    int buf = 0;
    for (int k0 = 0; k0 < K; k0 += 16) {
        *(float4*)&As[buf][lr][lk]      = cvt4(a0);
        *(float4*)&As[buf][lr + 64][lk] = cvt4(a1);
        *(float4*)&Bs[buf][lr][lk]      = cvt4(b0);
        *(float4*)&Bs[buf][lr + 64][lk] = cvt4(b1);
        __syncthreads();
        if (k0 + 16 < K) {
            a0 = *(const float4*)(arow0 + k0 + 16);
            a1 = *(const float4*)(arow1 + k0 + 16);
            b0 = *(const float4*)(wrow0 + k0 + 16);
            b1 = *(const float4*)(wrow1 + k0 + 16);
        }
#pragma unroll
        for (int ks = 0; ks < 2; ks++) {
            float af[2][4], bf[8][2];
#pragma unroll
            for (int mt = 0; mt < 2; mt++) {
                const float* p0 = &As[buf][wm + mt * 16 + g][ks * 8 + tg];
                const float* p1 = &As[buf][wm + mt * 16 + g + 8][ks * 8 + tg];
                af[mt][0] = p0[0]; af[mt][1] = p1[0];
                af[mt][2] = p0[4]; af[mt][3] = p1[4];
            }
#pragma unroll
            for (int nt = 0; nt < 8; nt++) {
                const float* p = &Bs[buf][wn + nt * 8 + g][ks * 8 + tg];
                bf[nt][0] = p[0]; bf[nt][1] = p[4];
            }
#pragma unroll
            for (int mt = 0; mt < 2; mt++)
#pragma unroll
                for (int nt = 0; nt < 8; nt++)
                    mma_tf32(acc[mt][nt], af[mt], bf[nt]);
        }
        buf ^= 1;
    }

#pragma unroll
    for (int mt = 0; mt < 2; mt++) {
        int m0 = bm + wm + mt * 16 + g;
#pragma unroll
        for (int half = 0; half < 2; half++) {
            int m = m0 + half * 8;
            size_t orow = (Sremap > 0) ? ((size_t)(m & 31) * Sremap + (size_t)(m >> 5)) : (size_t)m;
            float* crow = C + orow * (size_t)N;
#pragma unroll
            for (int nt = 0; nt < 8; nt++) {
                int col = bn + wn + nt * 8 + tg * 2;
                float bv0 = bias ? bias[col]     : 0.f;
                float bv1 = bias ? bias[col + 1] : 0.f;
                float2 v;
                v.x = acc[mt][nt][half * 2 + 0] + bv0;
                v.y = acc[mt][nt][half * 2 + 1] + bv1;
                *(float2*)&crow[col] = v;
            }
        }
    }
}

// ================= persistent encoder (unchanged) =================
__global__ void __launch_bounds__(256) enc_persistent(
    const float* __restrict__ Whh, const float* __restrict__ bhh,
    const int* __restrict__ enclen)
{
    extern __shared__ float dyn[];
    float* wt = dyn;              // [1024][25]
    float* hs = dyn + 1024 * 25;  // [32][132]
    __shared__ unsigned s_base;
    int tid = threadIdx.x, bid = blockIdx.x;
    if (tid == 0) s_base = *(volatile unsigned*)&g_bar_sense;

    int j0 = bid * 8;
#pragma unroll 1
    for (int r = 0; r < 24; r++) {
        int g = r >> 3, j = r & 7;
        const float* wrow = Whh + (size_t)(g * 1024 + j0 + j) * 1024;
        for (int k = tid; k < 1024; k += 256)
            wt[k * 25 + j * 3 + g] = wrow[k];
    }
    __syncthreads();
    unsigned ep = s_base;

    int b  = tid >> 3;
    int jj = tid & 7;
    int jg = j0 + jj;
    float br = bhh[jg], bz = bhh[1024 + jg], bn_ = bhh[2048 + jg];
    int len = enclen[b];

    int lb = tid >> 3;
    int lk = (tid & 7) << 4;

    for (int t = 0; t < SEe; t++) {
        const float* h  = (t & 1) ? g_h1 : g_h0;
        float*       hn = (t & 1) ? g_h0 : g_h1;

        float accr = br, accz = bz, accn = bn_;
        const float* hrow = h + (size_t)lb * 1024;
        float4 p0 = *(const float4*)(hrow + lk);
        float4 p1 = *(const float4*)(hrow + lk + 4);
        float4 p2 = *(const float4*)(hrow + lk + 8);
        float4 p3 = *(const float4*)(hrow + lk + 12);

        const float* hb = hs + b * 132;
#pragma unroll 1
        for (int c = 0; c < 8; c++) {
            __syncthreads();
            float* hd = hs + lb * 132 + lk;
            *(float4*)(hd)      = p0;
            *(float4*)(hd + 4)  = p1;
            *(float4*)(hd + 8)  = p2;
            *(float4*)(hd + 12) = p3;
            __syncthreads();
            if (c < 7) {
                const float* src = hrow + (c + 1) * 128 + lk;
                p0 = *(const float4*)(src);
                p1 = *(const float4*)(src + 4);
                p2 = *(const float4*)(src + 8);
                p3 = *(const float4*)(src + 12);
            }
            const float* wb = wt + (size_t)(c * 128) * 25 + jj * 3;
#pragma unroll 8
            for (int kk = 0; kk < 128; kk++) {
                float a = hb[kk];
                accr += a * wb[kk * 25 + 0];
                accz += a * wb[kk * 25 + 1];
                accn += a * wb[kk * 25 + 2];
            }
        }

        const float* gi = g_enc_gi + ((size_t)t * Bb + b) * G3;
        float r = sigf(gi[jg] + accr);
        float z = sigf(gi[1024 + jg] + accz);
        float n = tanhf(gi[2048 + jg] + r * accn);
        float hold = h[b * 1024 + jg];
        float hnv = (1.f - z) * n + z * hold;
        bool msk = t < len;
        hn[b * 1024 + jg] = msk ? hnv : hold;
        g_enc_out[(size_t)t * Bb * Hh + b * 1024 + jg] = msk ? hnv : 0.f;
        grid_bar(++ep, NBE);
    }
}

// ================= persistent decoder: register-resident weights =================
// thread = (ks = tid>>3 in 0..31, jj = tid&7). Thread holds wr/wz/wn[64] registers
// covering u-slice [ks*64, ks*64+64) of u = [h(1024) | ctx(1024)], rows j0+jj (+1024,+2048).
// P3 stage layout: us[b*2176 + (k>>6)*68 + (k&63)] — chunk-padded, float4-aligned
// (the previous k+(k>>6) swizzle broke 16B alignment -> misaligned-address trap).
__global__ void __launch_bounds__(256) dec_persistent(
    const float* __restrict__ Whh, const float* __restrict__ Wih,
    const float* __restrict__ bhh)
{
    extern __shared__ float dyn[];
    float* us = dyn;                 // [4][2176] padded stage (P3) / h cache (P1)
    float* pt = dyn + 4 * 2176;      // [768][36] partials
    __shared__ float sc[SEe];
    __shared__ float red[8];
    __shared__ unsigned s_base;
    int tid = threadIdx.x, bid = blockIdx.x, lane = tid & 31, warp = tid >> 5;
    if (tid == 0) s_base = *(volatile unsigned*)&g_bar_sense;

    int j0 = bid * 8;
    int ks = tid >> 3;
    int jj = tid & 7;
    int jg = j0 + jj;

    // ---- preload weight slices into registers (held across all 128 steps) ----
    float wr[64], wz[64], wn[64];
    {
        const float* Wc = Wih + Ee;           // ctx cols of dec_Wih, row stride 2048
        int k0 = ks * 64;
#pragma unroll
        for (int i = 0; i < 64; i += 4) {
            int gk = k0 + i;
            float4 vr, vz, vn;
            if (gk < 1024) {
                vr = *(const float4*)(Whh + (size_t)jg * 1024 + gk);
                vz = *(const float4*)(Whh + (size_t)(1024 + jg) * 1024 + gk);
                vn = *(const float4*)(Whh + (size_t)(2048 + jg) * 1024 + gk);
            } else {
                vr = *(const float4*)(Wc + (size_t)jg * 2048 + gk - 1024);
                vz = *(const float4*)(Wc + (size_t)(1024 + jg) * 2048 + gk - 1024);
                vn = *(const float4*)(Wc + (size_t)(2048 + jg) * 2048 + gk - 1024);
            }
            wr[i] = vr.x; wr[i + 1] = vr.y; wr[i + 2] = vr.z; wr[i + 3] = vr.w;
            wz[i] = vz.x; wz[i + 1] = vz.y; wz[i + 2] = vz.z; wz[i + 3] = vz.w;
            wn[i] = vn.x; wn[i + 1] = vn.y; wn[i + 2] = vn.z; wn[i + 3] = vn.w;
        }
    }

    int gb = tid >> 3;                       // gate-phase batch (same extraction as ks)
    float br = bhh[jg], bz = bhh[1024 + jg], bn_ = bhh[2048 + jg];

    int pb = bid >> 2;                       // P1/P2 batch (4 blocks per batch)
    int quarter = bid & 3;

    __syncthreads();
    unsigned ep = s_base;

    for (int t = 0; t < SDd; t++) {
        const float* h  = (t & 1) ? g_h1 : g_h0;
        float*       hn = (t & 1) ? g_h0 : g_h1;

        // ---- P1: scores[pb][s] = Mk[pb,s,:] . h[pb] + sb0 ----
        {
            ((float4*)us)[tid] = ((const float4*)(h + (size_t)pb * 1024))[tid];
            __syncthreads();
            const float4* hv = (const float4*)us;
            int s0 = quarter * 64;
            for (int s = s0 + warp; s < s0 + 64; s += 8) {
                int m = pb * 256 + s;
                const float4* mk = (const float4*)(g_Mk + (size_t)m * 1024);
                float a = 0.f;
#pragma unroll
                for (int i = 0; i < 8; i++) {
                    float4 kv = mk[lane + 32 * i];
                    float4 qv = hv[lane + 32 * i];
                    a += kv.x * qv.x + kv.y * qv.y + kv.z * qv.z + kv.w * qv.w;
                }
#pragma unroll
                for (int o = 16; o > 0; o >>= 1) a += __shfl_xor_sync(0xffffffffu, a, o);
                if (lane == 0) g_sc[m] = a + g_sb0[m];
            }
        }
        grid_bar(++ep, NBD);

        // ---- P2: softmax (redundant per block) + ctx quarter ----
        {
            float v = g_sc[pb * 256 + tid];
            float m = v;
#pragma unroll
            for (int o = 16; o > 0; o >>= 1) m = fmaxf(m, __shfl_xor_sync(0xffffffffu, m, o));
            if (lane == 0) red[warp] = m;
            __syncthreads();
            float mm = red[0];
#pragma unroll
            for (int i = 1; i < 8; i++) mm = fmaxf(mm, red[i]);
            float e = expf(v - mm);
            float ssum = e;
#pragma unroll
            for (int o = 16; o > 0; o >>= 1) ssum += __shfl_xor_sync(0xffffffffu, ssum, o);
            __syncthreads();
            if (lane == 0) red[warp] = ssum;
            __syncthreads();
            float tot = 0.f;
#pragma unroll
            for (int i = 0; i < 8; i++) tot += red[i];
            sc[tid] = e / tot;
            __syncthreads();

            int c0 = quarter * 256 + tid;
            float s0 = 0.f;
#pragma unroll 8
            for (int s = 0; s < SEe; s++)
                s0 += sc[s] * g_enc_out[(size_t)s * Bb * Hh + pb * 1024 + c0];
            g_ctx[(size_t)pb * 1024 + c0] = s0;
        }
        grid_bar(++ep, NBD);

        // ---- P3: register-weight accumulation, 8 groups of 4 batches ----
#pragma unroll 1
        for (int g8 = 0; g8 < 8; g8++) {
            int b0 = g8 * 4;
            __syncthreads();
            // stage u[4][2048] chunk-padded: us[b*2176 + (k>>6)*68 + (k&63)]
#pragma unroll
            for (int i = 0; i < 8; i++) {
                int idx = (tid + i * 256) * 4;           // 0..8188
                int b = idx >> 11, k = idx & 2047;
                const float* src = (k < 1024)
                    ? (h + (size_t)(b0 + b) * 1024 + k)
                    : (g_ctx + (size_t)(b0 + b) * 1024 + (k - 1024));
                float4 v = *(const float4*)src;
                *(float4*)&us[b * 2176 + (k >> 6) * 68 + (k & 63)] = v;
            }
            __syncthreads();

            float ar[4], az[4], an[4];
#pragma unroll
            for (int b = 0; b < 4; b++) {
                float sr = 0.f, sz = 0.f, sn = 0.f;
                const float* ub = us + b * 2176 + ks * 68;
#pragma unroll
                for (int kk = 0; kk < 64; kk++) {
                    float a = ub[kk];
                    sr += a * wr[kk];
                    sz += a * wz[kk];
                    sn += a * wn[kk];
                }
                ar[b] = sr; az[b] = sz; an[b] = sn;
            }
#pragma unroll
            for (int b = 0; b < 4; b++) {
                int ob = (b0 + b) * 3;
                pt[(size_t)((ob + 0) * 8 + jj) * 36 + ks] = ar[b];
                pt[(size_t)((ob + 1) * 8 + jj) * 36 + ks] = az[b];
                pt[(size_t)((ob + 2) * 8 + jj) * 36 + ks] = an[b];
            }
        }
        __syncthreads();

        // ---- reduce partials + gate (thread -> (gb, jj)) ----
        {
            const float* pr = pt + (size_t)((gb * 3 + 0) * 8 + jj) * 36;
            const float* pz = pt + (size_t)((gb * 3 + 1) * 8 + jj) * 36;
            const float* pn = pt + (size_t)((gb * 3 + 2) * 8 + jj) * 36;
            float sr = 0.f, sz = 0.f, sn0 = 0.f, sn1 = 0.f;
#pragma unroll
            for (int i = 0; i < 32; i += 4) {
                float4 v = *(const float4*)(pr + i);
                sr += v.x + v.y + v.z + v.w;
                float4 w = *(const float4*)(pz + i);
                sz += w.x + w.y + w.z + w.w;
            }
#pragma unroll
            for (int i = 0; i < 16; i += 4) {
                float4 v = *(const float4*)(pn + i);
                sn0 += v.x + v.y + v.z + v.w;       // h part (ks<16)
            }
#pragma unroll
            for (int i = 16; i < 32; i += 4) {
                float4 v = *(const float4*)(pn + i);
                sn1 += v.x + v.y + v.z + v.w;       // ctx part (ks>=16)
            }
            const float* gx = g_dec_gx + ((size_t)t * Bb + gb) * G3;
            float r = sigf(gx[jg] + sr + br);
            float z = sigf(gx[1024 + jg] + sz + bz);
            float n = tanhf(gx[2048 + jg] + sn1 + r * (sn0 + bn_));
            float hold = h[gb * 1024 + jg];
            float h2 = (1.f - z) * n + z * hold;
            hn[gb * 1024 + jg] = h2;
            g_dec_out[(size_t)t * Bb * Hh + gb * 1024 + jg] = h2;
        }
        grid_bar(++ep, NBD);
    }
}

extern "C" void kernel_launch(void* const* d_in, const int* in_sizes, int n_in,
                              void* d_out, int out_size)
{
    const int*   enc_in   = (const int*)d_in[0];
    const int*   dec_in   = (const int*)d_in[1];
    const int*   enc_len  = (const int*)d_in[2];
    const float* emb      = (const float*)d_in[4];
    const float* enc_Wih  = (const float*)d_in[5];
    const float* enc_Whh  = (const float*)d_in[6];
    const float* enc_bih  = (const float*)d_in[7];
    const float* enc_bhh  = (const float*)d_in[8];
    const float* dec_Wih  = (const float*)d_in[9];
    const float* dec_Whh  = (const float*)d_in[10];
    const float* dec_bih  = (const float*)d_in[11];
    const float* dec_bhh  = (const float*)d_in[12];
    const float* attn_kW  = (const float*)d_in[13];
    const float* attn_kb  = (const float*)d_in[14];
    const float* attn_qW  = (const float*)d_in[15];
    const float* attn_qb  = (const float*)d_in[16];
    const float* logits_W = (const float*)d_in[17];
    const float* logits_b = (const float*)d_in[18];
    float* out = (float*)d_out;
    (void)in_sizes; (void)n_in; (void)out_size;

    float *p_enc_gi, *p_dec_gx, *p_enc_out, *p_kT, *p_Mk, *p_qWT, *p_dec_out;
    int *p_enc_rows, *p_dec_rows;
    cudaGetSymbolAddress((void**)&p_enc_gi,  g_enc_gi);
    cudaGetSymbolAddress((void**)&p_dec_gx,  g_dec_gx);
    cudaGetSymbolAddress((void**)&p_enc_out, g_enc_out);
    cudaGetSymbolAddress((void**)&p_kT,      g_kT);
    cudaGetSymbolAddress((void**)&p_Mk,      g_Mk);
    cudaGetSymbolAddress((void**)&p_qWT,     g_qWT);
    cudaGetSymbolAddress((void**)&p_dec_out, g_dec_out);
    cudaGetSymbolAddress((void**)&p_enc_rows, g_enc_rows);
    cudaGetSymbolAddress((void**)&p_dec_rows, g_dec_rows);

    const int enc_smem = (1024 * 25 + 32 * 132) * 4;          // 119,296 B
    const int dec_smem = (4 * 2176 + 768 * 36) * 4;           // 145,408 B
    cudaFuncSetAttribute(enc_persistent,
                         cudaFuncAttributeMaxDynamicSharedMemorySize, enc_smem);
    cudaFuncSetAttribute(dec_persistent,
                         cudaFuncAttributeMaxDynamicSharedMemorySize, dec_smem);

    build_rows_kernel<<<32, 256>>>(enc_in, dec_in);
    init_h_kernel<<<(Bb * Hh) / 256, 256>>>();

    gemm_tf32<<<dim3(G3 / 128, (SEe * Bb) / 128), 256>>>(
        emb, p_enc_rows, Ee, enc_Wih, Ee, enc_bih, p_enc_gi, G3, Ee, 0);

    enc_persistent<<<NBE, 256, enc_smem>>>(enc_Whh, enc_bhh, enc_len);

    // kT = enc_out @ kW.T + kb
    gemm_tf32<<<dim3(Hh / 128, (SEe * Bb) / 128), 256>>>(
        p_enc_out, nullptr, Hh, attn_kW, Hh, attn_kb, p_kT, Hh, Hh, SEe);

    // Mk = kT @ qW, sb0 = kT . qb
    transpose_qw<<<dim3(32, 32), 256>>>(attn_qW);
    gemm_tf32<<<dim3(Hh / 128, (Bb * SEe) / 128), 256>>>(
        p_kT, nullptr, Hh, p_qWT, Hh, nullptr, p_Mk, Hh, Hh, 0);
    sb0_kernel<<<(Bb * SEe) / 8, 256>>>(attn_qb);

    gemm_tf32<<<dim3(G3 / 128, (SDd * Bb) / 128), 256>>>(
        emb, p_dec_rows, Ee, dec_Wih, Ee + Hh, dec_bih, p_dec_gx, G3, Ee, 0);

    dec_persistent<<<NBD, 256, dec_smem>>>(dec_Whh, dec_Wih, dec_bhh);

    gemm_tf32<<<dim3(Vv / 128, (SDd * Bb) / 128), 256>>>(
        p_dec_out, nullptr, Hh, logits_W, Hh, logits_b, out, Vv, Hh, SDd);
}

// round 17
// speedup vs baseline: 2.0253x; 1.0229x over previous
#include <cuda_runtime.h>
#include <cstdint>
#include <cstddef>

#define Vv   32000
#define Ee   1024
#define Hh   1024
#define Bb   32
#define SEe  256
#define SDd  128
#define G3   3072
#define NBE  128
#define NBD  128

__device__ float g_enc_gi[(size_t)SEe * Bb * G3];
__device__ float g_dec_gx[(size_t)SDd * Bb * G3];
__device__ float g_enc_out[(size_t)SEe * Bb * Hh];
__device__ float g_kT[(size_t)Bb * SEe * Hh];
__device__ float g_Mk[(size_t)Bb * SEe * Hh];
__device__ float g_qWT[(size_t)Hh * Hh];
__device__ float g_sb0[Bb * SEe];
__device__ float g_dec_out[(size_t)SDd * Bb * Hh];
__device__ float g_h0[Bb * Hh];
__device__ float g_h1[Bb * Hh];
__device__ float g_ctx[Bb * Hh];
__device__ float g_sc[Bb * SEe];
__device__ int   g_enc_rows[SEe * Bb];
__device__ int   g_dec_rows[SDd * Bb];
__device__ unsigned g_bar_count;
__device__ unsigned g_bar_sense;

__device__ __forceinline__ float sigf(float x) { return 1.f / (1.f + expf(-x)); }

// software grid barrier, nanosleep spin (tight spin regressed via DVFS clock drop)
__device__ __forceinline__ void grid_bar(unsigned target, unsigned nblk)
{
    __syncthreads();
    if (threadIdx.x == 0) {
        __threadfence();
        if (atomicAdd(&g_bar_count, 1u) == nblk - 1) {
            atomicExch(&g_bar_count, 0u);
            __threadfence();
            atomicExch(&g_bar_sense, target);
        } else {
            while (*(volatile unsigned*)&g_bar_sense < target) __nanosleep(64);
            __threadfence();
        }
    }
    __syncthreads();
}

__global__ void __launch_bounds__(256) build_rows_kernel(
    const int* __restrict__ enc_in, const int* __restrict__ dec_in)
{
    int m = blockIdx.x * 256 + threadIdx.x;
    if (m < SEe * Bb) {
        int t = m >> 5, b = m & 31;
        g_enc_rows[m] = enc_in[b * SEe + t];
    }
    if (m < SDd * Bb) {
        int t = m >> 5, b = m & 31;
        g_dec_rows[m] = dec_in[b * SDd + t];
    }
}

__global__ void __launch_bounds__(256) init_h_kernel()
{
    int i = blockIdx.x * 256 + threadIdx.x;
    if (i < Bb * Hh) g_h0[i] = 0.f;
}

// transpose qW (1024x1024) -> g_qWT
__global__ void __launch_bounds__(256) transpose_qw(const float* __restrict__ qW)
{
    __shared__ float tile[32][33];
    int bx = blockIdx.x * 32, by = blockIdx.y * 32;
    int tx = threadIdx.x & 31, ty = threadIdx.x >> 5;
#pragma unroll
    for (int i = 0; i < 32; i += 8)
        tile[ty + i][tx] = qW[(size_t)(by + ty + i) * Hh + bx + tx];
    __syncthreads();
#pragma unroll
    for (int i = 0; i < 32; i += 8)
        g_qWT[(size_t)(bx + ty + i) * Hh + by + tx] = tile[tx][ty + i];
}

// sb0[m] = kT[m,:] . qb
__global__ void __launch_bounds__(256) sb0_kernel(const float* __restrict__ qb)
{
    int m = blockIdx.x * 8 + (threadIdx.x >> 5);
    int lane = threadIdx.x & 31;
    const float4* kr = (const float4*)(g_kT + (size_t)m * Hh);
    const float4* qr = (const float4*)qb;
    float a = 0.f;
#pragma unroll
    for (int i = 0; i < 8; i++) {
        float4 kv = kr[lane + 32 * i];
        float4 qv = qr[lane + 32 * i];
        a += kv.x * qv.x + kv.y * qv.y + kv.z * qv.z + kv.w * qv.w;
    }
#pragma unroll
    for (int o = 16; o > 0; o >>= 1) a += __shfl_xor_sync(0xffffffffu, a, o);
    if (lane == 0) g_sb0[m] = a;
}

// ================= tf32 tensor-core GEMM =================
__device__ __forceinline__ float to_tf32(float x)
{
    uint32_t u;
    asm("cvt.rna.tf32.f32 %0, %1;" : "=r"(u) : "f"(x));
    return __uint_as_float(u);
}

__device__ __forceinline__ float4 cvt4(float4 v)
{
    float4 r;
    r.x = to_tf32(v.x); r.y = to_tf32(v.y); r.z = to_tf32(v.z); r.w = to_tf32(v.w);
    return r;
}

__device__ __forceinline__ void mma_tf32(float* c, const float* a, const float* b)
{
    asm volatile(
        "mma.sync.aligned.m16n8k8.row.col.f32.tf32.tf32.f32 "
        "{%0,%1,%2,%3}, {%4,%5,%6,%7}, {%8,%9}, {%0,%1,%2,%3};"
        : "+f"(c[0]), "+f"(c[1]), "+f"(c[2]), "+f"(c[3])
        : "r"(__float_as_uint(a[0])), "r"(__float_as_uint(a[1])),
          "r"(__float_as_uint(a[2])), "r"(__float_as_uint(a[3])),
          "r"(__float_as_uint(b[0])), "r"(__float_as_uint(b[1])));
}

__global__ void __launch_bounds__(256) gemm_tf32(
    const float* __restrict__ A, const int* __restrict__ arows, int lda,
    const float* __restrict__ W, int ldw,
    const float* __restrict__ bias,
    float* __restrict__ C, int N, int K, int Sremap)
{
    __shared__ __align__(16) float As[2][128][20];
    __shared__ __align__(16) float Bs[2][128][20];

    int tid = threadIdx.x;
    int bm = blockIdx.y * 128, bn = blockIdx.x * 128;
    int lr = tid >> 2;
    int lk = (tid & 3) << 2;

    int ar0 = arows ? arows[bm + lr] : bm + lr;
    int ar1 = arows ? arows[bm + lr + 64] : bm + lr + 64;
    const float* arow0 = A + (size_t)ar0 * lda + lk;
    const float* arow1 = A + (size_t)ar1 * lda + lk;
    const float* wrow0 = W + (size_t)(bn + lr) * ldw + lk;
    const float* wrow1 = W + (size_t)(bn + lr + 64) * ldw + lk;

    int warp = tid >> 5, lane = tid & 31;
    int wm = (warp >> 1) * 32, wn = (warp & 1) * 64;
    int g = lane >> 2, tg = lane & 3;

    float acc[2][8][4];
#pragma unroll
    for (int mt = 0; mt < 2; mt++)
#pragma unroll
        for (int nt = 0; nt < 8; nt++)
#pragma unroll
            for (int i = 0; i < 4; i++) acc[mt][nt][i] = 0.f;

    float4 a0 = *(const float4*)arow0;
    float4 a1 = *(const float4*)arow1;
    float4 b0 = *(const float4*)wrow0;
    float4 b1 = *(const float4*)wrow1;

    int buf = 0;
    for (int k0 = 0; k0 < K; k0 += 16) {
        *(float4*)&As[buf][lr][lk]      = cvt4(a0);
        *(float4*)&As[buf][lr + 64][lk] = cvt4(a1);
        *(float4*)&Bs[buf][lr][lk]      = cvt4(b0);
        *(float4*)&Bs[buf][lr + 64][lk] = cvt4(b1);
        __syncthreads();
        if (k0 + 16 < K) {
            a0 = *(const float4*)(arow0 + k0 + 16);
            a1 = *(const float4*)(arow1 + k0 + 16);
            b0 = *(const float4*)(wrow0 + k0 + 16);
            b1 = *(const float4*)(wrow1 + k0 + 16);
        }
#pragma unroll
        for (int ks = 0; ks < 2; ks++) {
            float af[2][4], bf[8][2];
#pragma unroll
            for (int mt = 0; mt < 2; mt++) {
                const float* p0 = &As[buf][wm + mt * 16 + g][ks * 8 + tg];
                const float* p1 = &As[buf][wm + mt * 16 + g + 8][ks * 8 + tg];
                af[mt][0] = p0[0]; af[mt][1] = p1[0];
                af[mt][2] = p0[4]; af[mt][3] = p1[4];
            }
#pragma unroll
            for (int nt = 0; nt < 8; nt++) {
                const float* p = &Bs[buf][wn + nt * 8 + g][ks * 8 + tg];
                bf[nt][0] = p[0]; bf[nt][1] = p[4];
            }
#pragma unroll
            for (int mt = 0; mt < 2; mt++)
#pragma unroll
                for (int nt = 0; nt < 8; nt++)
                    mma_tf32(acc[mt][nt], af[mt], bf[nt]);
        }
        buf ^= 1;
    }

#pragma unroll
    for (int mt = 0; mt < 2; mt++) {
        int m0 = bm + wm + mt * 16 + g;
#pragma unroll
        for (int half = 0; half < 2; half++) {
            int m = m0 + half * 8;
            size_t orow = (Sremap > 0) ? ((size_t)(m & 31) * Sremap + (size_t)(m >> 5)) : (size_t)m;
            float* crow = C + orow * (size_t)N;
#pragma unroll
            for (int nt = 0; nt < 8; nt++) {
                int col = bn + wn + nt * 8 + tg * 2;
                float bv0 = bias ? bias[col]     : 0.f;
                float bv1 = bias ? bias[col + 1] : 0.f;
                float2 v;
                v.x = acc[mt][nt][half * 2 + 0] + bv0;
                v.y = acc[mt][nt][half * 2 + 1] + bv1;
                *(float2*)&crow[col] = v;
            }
        }
    }
}

// ================= persistent encoder (unchanged) =================
__global__ void __launch_bounds__(256) enc_persistent(
    const float* __restrict__ Whh, const float* __restrict__ bhh,
    const int* __restrict__ enclen)
{
    extern __shared__ float dyn[];
    float* wt = dyn;              // [1024][25]
    float* hs = dyn + 1024 * 25;  // [32][132]
    __shared__ unsigned s_base;
    int tid = threadIdx.x, bid = blockIdx.x;
    if (tid == 0) s_base = *(volatile unsigned*)&g_bar_sense;

    int j0 = bid * 8;
#pragma unroll 1
    for (int r = 0; r < 24; r++) {
        int g = r >> 3, j = r & 7;
        const float* wrow = Whh + (size_t)(g * 1024 + j0 + j) * 1024;
        for (int k = tid; k < 1024; k += 256)
            wt[k * 25 + j * 3 + g] = wrow[k];
    }
    __syncthreads();
    unsigned ep = s_base;

    int b  = tid >> 3;
    int jj = tid & 7;
    int jg = j0 + jj;
    float br = bhh[jg], bz = bhh[1024 + jg], bn_ = bhh[2048 + jg];
    int len = enclen[b];

    int lb = tid >> 3;
    int lk = (tid & 7) << 4;

    for (int t = 0; t < SEe; t++) {
        const float* h  = (t & 1) ? g_h1 : g_h0;
        float*       hn = (t & 1) ? g_h0 : g_h1;

        float accr = br, accz = bz, accn = bn_;
        const float* hrow = h + (size_t)lb * 1024;
        float4 p0 = *(const float4*)(hrow + lk);
        float4 p1 = *(const float4*)(hrow + lk + 4);
        float4 p2 = *(const float4*)(hrow + lk + 8);
        float4 p3 = *(const float4*)(hrow + lk + 12);

        const float* hb = hs + b * 132;
#pragma unroll 1
        for (int c = 0; c < 8; c++) {
            __syncthreads();
            float* hd = hs + lb * 132 + lk;
            *(float4*)(hd)      = p0;
            *(float4*)(hd + 4)  = p1;
            *(float4*)(hd + 8)  = p2;
            *(float4*)(hd + 12) = p3;
            __syncthreads();
            if (c < 7) {
                const float* src = hrow + (c + 1) * 128 + lk;
                p0 = *(const float4*)(src);
                p1 = *(const float4*)(src + 4);
                p2 = *(const float4*)(src + 8);
                p3 = *(const float4*)(src + 12);
            }
            const float* wb = wt + (size_t)(c * 128) * 25 + jj * 3;
#pragma unroll 8
            for (int kk = 0; kk < 128; kk++) {
                float a = hb[kk];
                accr += a * wb[kk * 25 + 0];
                accz += a * wb[kk * 25 + 1];
                accn += a * wb[kk * 25 + 2];
            }
        }

        const float* gi = g_enc_gi + ((size_t)t * Bb + b) * G3;
        float r = sigf(gi[jg] + accr);
        float z = sigf(gi[1024 + jg] + accz);
        float n = tanhf(gi[2048 + jg] + r * accn);
        float hold = h[b * 1024 + jg];
        float hnv = (1.f - z) * n + z * hold;
        bool msk = t < len;
        hn[b * 1024 + jg] = msk ? hnv : hold;
        g_enc_out[(size_t)t * Bb * Hh + b * 1024 + jg] = msk ? hnv : 0.f;
        grid_bar(++ep, NBE);
    }
}

// ================= persistent decoder: gh moved into P1 =================
// thread = (ksA = tid>>3 in 0..31, jj = tid&7). Registers hold 32-wide slices
// of h-part (w*A) and ctx-part (w*B) weights for rows j0+jj (+1024,+2048).
// P1: scores quarter + gh (h-part) partials.  P2: softmax + ctx quarter.
// P3: reduce gh partials -> regs, gc (ctx-part) partials, reduce, gate.
__global__ void __launch_bounds__(256) dec_persistent(
    const float* __restrict__ Whh, const float* __restrict__ Wih,
    const float* __restrict__ bhh)
{
    extern __shared__ float dyn[];
    float* us = dyn;                 // [4][1152] padded stage / h cache (P1 scores)
    float* pt = dyn + 4 * 1152;      // [768][36] partials
    __shared__ float sc[SEe];
    __shared__ float red[8];
    __shared__ unsigned s_base;
    int tid = threadIdx.x, bid = blockIdx.x, lane = tid & 31, warp = tid >> 5;
    if (tid == 0) s_base = *(volatile unsigned*)&g_bar_sense;

    int j0 = bid * 8;
    int ksA = tid >> 3;              // 0..31, 32-wide k-slice
    int jj  = tid & 7;
    int jg  = j0 + jj;

    // ---- preload weight slices into registers (held across all 128 steps) ----
    float wrA[32], wzA[32], wnA[32];   // h-part:  k in [ksA*32, +32)
    float wrB[32], wzB[32], wnB[32];   // ctx-part: same k range of Wc
    {
        const float* Wc = Wih + Ee;    // ctx cols of dec_Wih, row stride 2048
        int k0 = ksA * 32;
#pragma unroll
        for (int i = 0; i < 32; i += 4) {
            float4 v;
            v = *(const float4*)(Whh + (size_t)jg * 1024 + k0 + i);
            wrA[i] = v.x; wrA[i+1] = v.y; wrA[i+2] = v.z; wrA[i+3] = v.w;
            v = *(const float4*)(Whh + (size_t)(1024 + jg) * 1024 + k0 + i);
            wzA[i] = v.x; wzA[i+1] = v.y; wzA[i+2] = v.z; wzA[i+3] = v.w;
            v = *(const float4*)(Whh + (size_t)(2048 + jg) * 1024 + k0 + i);
            wnA[i] = v.x; wnA[i+1] = v.y; wnA[i+2] = v.z; wnA[i+3] = v.w;
            v = *(const float4*)(Wc + (size_t)jg * 2048 + k0 + i);
            wrB[i] = v.x; wrB[i+1] = v.y; wrB[i+2] = v.z; wrB[i+3] = v.w;
            v = *(const float4*)(Wc + (size_t)(1024 + jg) * 2048 + k0 + i);
            wzB[i] = v.x; wzB[i+1] = v.y; wzB[i+2] = v.z; wzB[i+3] = v.w;
            v = *(const float4*)(Wc + (size_t)(2048 + jg) * 2048 + k0 + i);
            wnB[i] = v.x; wnB[i+1] = v.y; wnB[i+2] = v.z; wnB[i+3] = v.w;
        }
    }

    int gb = tid >> 3;                // gate-phase batch (same extraction as ksA)
    float br = bhh[jg], bz = bhh[1024 + jg], bn_ = bhh[2048 + jg];

    int pb = bid >> 2;                // P1/P2 batch (4 blocks per batch)
    int quarter = bid & 3;

    __syncthreads();
    unsigned ep = s_base;

    for (int t = 0; t < SDd; t++) {
        const float* h  = (t & 1) ? g_h1 : g_h0;
        float*       hn = (t & 1) ? g_h0 : g_h1;

        // ---- P1a: scores[pb][s] = Mk[pb,s,:] . h[pb] + sb0 ----
        {
            ((float4*)us)[tid] = ((const float4*)(h + (size_t)pb * 1024))[tid];
            __syncthreads();
            const float4* hv = (const float4*)us;
            int s0 = quarter * 64;
            for (int s = s0 + warp; s < s0 + 64; s += 8) {
                int m = pb * 256 + s;
                const float4* mk = (const float4*)(g_Mk + (size_t)m * 1024);
                float a = 0.f;
#pragma unroll
                for (int i = 0; i < 8; i++) {
                    float4 kv = mk[lane + 32 * i];
                    float4 qv = hv[lane + 32 * i];
                    a += kv.x * qv.x + kv.y * qv.y + kv.z * qv.z + kv.w * qv.w;
                }
#pragma unroll
                for (int o = 16; o > 0; o >>= 1) a += __shfl_xor_sync(0xffffffffu, a, o);
                if (lane == 0) g_sc[m] = a + g_sb0[m];
            }
        }

        // ---- P1b: gh (h-part) partials, 8 groups of 4 batches ----
#pragma unroll 1
        for (int g8 = 0; g8 < 8; g8++) {
            int b0 = g8 * 4;
            __syncthreads();
            // stage h[4][1024]: us[b*1152 + (k>>5)*36 + (k&31)]
#pragma unroll
            for (int i = 0; i < 4; i++) {
                int idx = (tid + i * 256) * 4;           // 0..4092
                int b = idx >> 10, k = idx & 1023;
                float4 v = *(const float4*)(h + (size_t)(b0 + b) * 1024 + k);
                *(float4*)&us[b * 1152 + (k >> 5) * 36 + (k & 31)] = v;
            }
            __syncthreads();

            float ar[4], az[4], an[4];
#pragma unroll
            for (int b = 0; b < 4; b++) {
                float sr = 0.f, sz = 0.f, sn = 0.f;
                const float* ub = us + b * 1152 + ksA * 36;
#pragma unroll
                for (int kk = 0; kk < 32; kk++) {
                    float a = ub[kk];
                    sr += a * wrA[kk];
                    sz += a * wzA[kk];
                    sn += a * wnA[kk];
                }
                ar[b] = sr; az[b] = sz; an[b] = sn;
            }
#pragma unroll
            for (int b = 0; b < 4; b++) {
                int ob = (b0 + b) * 3;
                pt[(size_t)((ob + 0) * 8 + jj) * 36 + ksA] = ar[b];
                pt[(size_t)((ob + 1) * 8 + jj) * 36 + ksA] = az[b];
                pt[(size_t)((ob + 2) * 8 + jj) * 36 + ksA] = an[b];
            }
        }
        grid_bar(++ep, NBD);

        // ---- P2: softmax (redundant per block) + ctx quarter ----
        {
            float v = g_sc[pb * 256 + tid];
            float m = v;
#pragma unroll
            for (int o = 16; o > 0; o >>= 1) m = fmaxf(m, __shfl_xor_sync(0xffffffffu, m, o));
            if (lane == 0) red[warp] = m;
            __syncthreads();
            float mm = red[0];
#pragma unroll
            for (int i = 1; i < 8; i++) mm = fmaxf(mm, red[i]);
            float e = expf(v - mm);
            float ssum = e;
#pragma unroll
            for (int o = 16; o > 0; o >>= 1) ssum += __shfl_xor_sync(0xffffffffu, ssum, o);
            __syncthreads();
            if (lane == 0) red[warp] = ssum;
            __syncthreads();
            float tot = 0.f;
#pragma unroll
            for (int i = 0; i < 8; i++) tot += red[i];
            sc[tid] = e / tot;
            __syncthreads();

            int c0 = quarter * 256 + tid;
            float s0 = 0.f;
#pragma unroll 8
            for (int s = 0; s < SEe; s++)
                s0 += sc[s] * g_enc_out[(size_t)s * Bb * Hh + pb * 1024 + c0];
            g_ctx[(size_t)pb * 1024 + c0] = s0;
        }
        grid_bar(++ep, NBD);

        // ---- P3a: reduce gh partials into registers ----
        float srH, szH, snH;
        {
            const float* pr = pt + (size_t)((gb * 3 + 0) * 8 + jj) * 36;
            const float* pz = pt + (size_t)((gb * 3 + 1) * 8 + jj) * 36;
            const float* pn = pt + (size_t)((gb * 3 + 2) * 8 + jj) * 36;
            float sr = 0.f, sz = 0.f, sn = 0.f;
#pragma unroll
            for (int i = 0; i < 32; i += 4) {
                float4 v = *(const float4*)(pr + i);
                sr += v.x + v.y + v.z + v.w;
                float4 w = *(const float4*)(pz + i);
                sz += w.x + w.y + w.z + w.w;
                float4 u = *(const float4*)(pn + i);
                sn += u.x + u.y + u.z + u.w;
            }
            srH = sr; szH = sz; snH = sn;
        }

        // ---- P3b: gc (ctx-part) partials, 8 groups of 4 batches ----
#pragma unroll 1
        for (int g8 = 0; g8 < 8; g8++) {
            int b0 = g8 * 4;
            __syncthreads();
#pragma unroll
            for (int i = 0; i < 4; i++) {
                int idx = (tid + i * 256) * 4;
                int b = idx >> 10, k = idx & 1023;
                float4 v = *(const float4*)(g_ctx + (size_t)(b0 + b) * 1024 + k);
                *(float4*)&us[b * 1152 + (k >> 5) * 36 + (k & 31)] = v;
            }
            __syncthreads();

            float ar[4], az[4], an[4];
#pragma unroll
            for (int b = 0; b < 4; b++) {
                float sr = 0.f, sz = 0.f, sn = 0.f;
                const float* ub = us + b * 1152 + ksA * 36;
#pragma unroll
                for (int kk = 0; kk < 32; kk++) {
                    float a = ub[kk];
                    sr += a * wrB[kk];
                    sz += a * wzB[kk];
                    sn += a * wnB[kk];
                }
                ar[b] = sr; az[b] = sz; an[b] = sn;
            }
#pragma unroll
            for (int b = 0; b < 4; b++) {
                int ob = (b0 + b) * 3;
                pt[(size_t)((ob + 0) * 8 + jj) * 36 + ksA] = ar[b];
                pt[(size_t)((ob + 1) * 8 + jj) * 36 + ksA] = az[b];
                pt[(size_t)((ob + 2) * 8 + jj) * 36 + ksA] = an[b];
            }
        }
        __syncthreads();

        // ---- P3c: reduce gc partials + gate ----
        {
            const float* pr = pt + (size_t)((gb * 3 + 0) * 8 + jj) * 36;
            const float* pz = pt + (size_t)((gb * 3 + 1) * 8 + jj) * 36;
            const float* pn = pt + (size_t)((gb * 3 + 2) * 8 + jj) * 36;
            float sr = 0.f, sz = 0.f, sn = 0.f;
#pragma unroll
            for (int i = 0; i < 32; i += 4) {
                float4 v = *(const float4*)(pr + i);
                sr += v.x + v.y + v.z + v.w;
                float4 w = *(const float4*)(pz + i);
                sz += w.x + w.y + w.z + w.w;
                float4 u = *(const float4*)(pn + i);
                sn += u.x + u.y + u.z + u.w;
            }
            const float* gx = g_dec_gx + ((size_t)t * Bb + gb) * G3;
            float r = sigf(gx[jg] + sr + srH + br);
            float z = sigf(gx[1024 + jg] + sz + szH + bz);
            float n = tanhf(gx[2048 + jg] + sn + r * (snH + bn_));
            float hold = h[gb * 1024 + jg];
            float h2 = (1.f - z) * n + z * hold;
            hn[gb * 1024 + jg] = h2;
            g_dec_out[(size_t)t * Bb * Hh + gb * 1024 + jg] = h2;
        }
        grid_bar(++ep, NBD);
    }
}

extern "C" void kernel_launch(void* const* d_in, const int* in_sizes, int n_in,
                              void* d_out, int out_size)
{
    const int*   enc_in   = (const int*)d_in[0];
    const int*   dec_in   = (const int*)d_in[1];
    const int*   enc_len  = (const int*)d_in[2];
    const float* emb      = (const float*)d_in[4];
    const float* enc_Wih  = (const float*)d_in[5];
    const float* enc_Whh  = (const float*)d_in[6];
    const float* enc_bih  = (const float*)d_in[7];
    const float* enc_bhh  = (const float*)d_in[8];
    const float* dec_Wih  = (const float*)d_in[9];
    const float* dec_Whh  = (const float*)d_in[10];
    const float* dec_bih  = (const float*)d_in[11];
    const float* dec_bhh  = (const float*)d_in[12];
    const float* attn_kW  = (const float*)d_in[13];
    const float* attn_kb  = (const float*)d_in[14];
    const float* attn_qW  = (const float*)d_in[15];
    const float* attn_qb  = (const float*)d_in[16];
    const float* logits_W = (const float*)d_in[17];
    const float* logits_b = (const float*)d_in[18];
    float* out = (float*)d_out;
    (void)in_sizes; (void)n_in; (void)out_size;

    float *p_enc_gi, *p_dec_gx, *p_enc_out, *p_kT, *p_Mk, *p_qWT, *p_dec_out;
    int *p_enc_rows, *p_dec_rows;
    cudaGetSymbolAddress((void**)&p_enc_gi,  g_enc_gi);
    cudaGetSymbolAddress((void**)&p_dec_gx,  g_dec_gx);
    cudaGetSymbolAddress((void**)&p_enc_out, g_enc_out);
    cudaGetSymbolAddress((void**)&p_kT,      g_kT);
    cudaGetSymbolAddress((void**)&p_Mk,      g_Mk);
    cudaGetSymbolAddress((void**)&p_qWT,     g_qWT);
    cudaGetSymbolAddress((void**)&p_dec_out, g_dec_out);
    cudaGetSymbolAddress((void**)&p_enc_rows, g_enc_rows);
    cudaGetSymbolAddress((void**)&p_dec_rows, g_dec_rows);

    const int enc_smem = (1024 * 25 + 32 * 132) * 4;          // 119,296 B
    const int dec_smem = (4 * 1152 + 768 * 36) * 4;           // 129,024 B
    cudaFuncSetAttribute(enc_persistent,
                         cudaFuncAttributeMaxDynamicSharedMemorySize, enc_smem);
    cudaFuncSetAttribute(dec_persistent,
                         cudaFuncAttributeMaxDynamicSharedMemorySize, dec_smem);

    build_rows_kernel<<<32, 256>>>(enc_in, dec_in);
    init_h_kernel<<<(Bb * Hh) / 256, 256>>>();

    gemm_tf32<<<dim3(G3 / 128, (SEe * Bb) / 128), 256>>>(
        emb, p_enc_rows, Ee, enc_Wih, Ee, enc_bih, p_enc_gi, G3, Ee, 0);

    enc_persistent<<<NBE, 256, enc_smem>>>(enc_Whh, enc_bhh, enc_len);

    // kT = enc_out @ kW.T + kb
    gemm_tf32<<<dim3(Hh / 128, (SEe * Bb) / 128), 256>>>(
        p_enc_out, nullptr, Hh, attn_kW, Hh, attn_kb, p_kT, Hh, Hh, SEe);

    // Mk = kT @ qW, sb0 = kT . qb
    transpose_qw<<<dim3(32, 32), 256>>>(attn_qW);
    gemm_tf32<<<dim3(Hh / 128, (Bb * SEe) / 128), 256>>>(
        p_kT, nullptr, Hh, p_qWT, Hh, nullptr, p_Mk, Hh, Hh, 0);
    sb0_kernel<<<(Bb * SEe) / 8, 256>>>(attn_qb);

    gemm_tf32<<<dim3(G3 / 128, (SDd * Bb) / 128), 256>>>(
        emb, p_dec_rows, Ee, dec_Wih, Ee + Hh, dec_bih, p_dec_gx, G3, Ee, 0);

    dec_persistent<<<NBD, 256, dec_smem>>>(dec_Whh, dec_Wih, dec_bhh);

    gemm_tf32<<<dim3(Vv / 128, (SDd * Bb) / 128), 256>>>(
        p_dec_out, nullptr, Hh, logits_W, Hh, logits_b, out, Vv, Hh, SDd);
}